// round 9
// baseline (speedup 1.0000x reference)
#include <cuda_runtime.h>
#include <cuda_bf16.h>
#include <cstdint>
#include <math.h>

#define M_TOK 8192
#define E_DIM 2048
#define F_DIM 8192
#define NW    16777216

// ---------------- device scratch ----------------
__device__ __nv_bfloat16 g_w1b[(size_t)F_DIM * E_DIM];
__device__ __nv_bfloat16 g_w2b[(size_t)F_DIM * E_DIM];
__device__ __nv_bfloat16 g_w3b[(size_t)E_DIM * F_DIM];
__device__ __nv_bfloat16 g_xb [(size_t)M_TOK * E_DIM];
__device__ __nv_bfloat16 g_hb [(size_t)M_TOK * F_DIM];
__device__ int8_t g_w1q[(size_t)F_DIM * E_DIM];
__device__ int8_t g_w2q[(size_t)F_DIM * E_DIM];
__device__ int8_t g_w3q[(size_t)E_DIM * F_DIM];
__device__ int8_t g_xq [(size_t)M_TOK * E_DIM];
__device__ int8_t g_hq [(size_t)M_TOK * F_DIM];
__device__ float  g_h  [(size_t)M_TOK * F_DIM];
__device__ float  g_inv_sx[M_TOK];
__device__ float  g_inv_sh[M_TOK];
__device__ double g_wpart[3 * 256];
__device__ float  g_wdq[3];
__device__ float  g_wsc[3];
__device__ int    g_flag1;    // GEMM1 IMMA bad?
__device__ int    g_flag2;    // GEMM2 IMMA bad?

// ---------------- prep kernels ----------------
__global__ void wabs_partial(const float* __restrict__ w, int n, int slot) {
    __shared__ double sd[256];
    int tid = threadIdx.x;
    double acc = 0.0;
    for (int i = blockIdx.x * 256 + tid; i < n; i += 256 * gridDim.x)
        acc += (double)fabsf(w[i]);
    sd[tid] = acc; __syncthreads();
    for (int s = 128; s > 0; s >>= 1) {
        if (tid < s) sd[tid] += sd[tid + s];
        __syncthreads();
    }
    if (tid == 0) g_wpart[slot * 256 + blockIdx.x] = sd[0];
}

__global__ void wscale_final() {
    __shared__ double sd[256];
    int tid = threadIdx.x;
    for (int wsel = 0; wsel < 3; wsel++) {
        sd[tid] = g_wpart[wsel * 256 + tid]; __syncthreads();
        for (int s = 128; s > 0; s >>= 1) {
            if (tid < s) sd[tid] += sd[tid + s];
            __syncthreads();
        }
        if (tid == 0) {
            float mean = (float)(sd[0] / (double)NW);
            float dq = fmaxf(mean, 1e-5f);
            g_wdq[wsel] = dq;
            g_wsc[wsel] = 1.0f / dq;
        }
        __syncthreads();
    }
}

__global__ void reset_flags() { g_flag1 = 0; g_flag2 = 0; }

// ternary weight quant -> int8 (SIGNED-SAFE: float -> int -> signed char) AND bf16
__global__ void quant_w(const float* __restrict__ w, int8_t* __restrict__ q,
                        __nv_bfloat16* __restrict__ qb, int n, int wi) {
    float s = g_wsc[wi];
    int i = (blockIdx.x * blockDim.x + threadIdx.x) * 4;
    if (i < n) {
        float4 v = *(const float4*)(w + i);
        int ia = (int)fminf(fmaxf(rintf(v.x * s), -1.0f), 1.0f);
        int ib = (int)fminf(fmaxf(rintf(v.y * s), -1.0f), 1.0f);
        int ic = (int)fminf(fmaxf(rintf(v.z * s), -1.0f), 1.0f);
        int id = (int)fminf(fmaxf(rintf(v.w * s), -1.0f), 1.0f);
        char4 o8;
        o8.x = (signed char)ia; o8.y = (signed char)ib;
        o8.z = (signed char)ic; o8.w = (signed char)id;
        *(char4*)(q + i) = o8;
        ushort4 ob;
        ob.x = __bfloat16_as_ushort(__float2bfloat16_rn((float)ia));
        ob.y = __bfloat16_as_ushort(__float2bfloat16_rn((float)ib));
        ob.z = __bfloat16_as_ushort(__float2bfloat16_rn((float)ic));
        ob.w = __bfloat16_as_ushort(__float2bfloat16_rn((float)id));
        *(ushort4*)(qb + i) = ob;
    }
}

template <int VE>
__global__ void act_quant(const float* __restrict__ in, int8_t* __restrict__ q,
                          __nv_bfloat16* __restrict__ qb,
                          float* __restrict__ inv, int rowlen) {
    int m = blockIdx.x, tid = threadIdx.x;
    const float4* row = (const float4*)(in + (size_t)m * rowlen);
    float4 v[VE / 4];
    float ss = 0.0f, mx = 0.0f;
#pragma unroll
    for (int j = 0; j < VE / 4; j++) {
        v[j] = row[tid + j * 256];
        ss += v[j].x * v[j].x + v[j].y * v[j].y + v[j].z * v[j].z + v[j].w * v[j].w;
        mx = fmaxf(mx, fmaxf(fmaxf(fabsf(v[j].x), fabsf(v[j].y)),
                             fmaxf(fabsf(v[j].z), fabsf(v[j].w))));
    }
    __shared__ float sss[256], smx[256];
    sss[tid] = ss; smx[tid] = mx; __syncthreads();
    for (int s = 128; s > 0; s >>= 1) {
        if (tid < s) {
            sss[tid] += sss[tid + s];
            smx[tid] = fmaxf(smx[tid], smx[tid + s]);
        }
        __syncthreads();
    }
    float r = rsqrtf(sss[0] / (float)rowlen + 1e-6f);
    float cmax = fmaxf(smx[0] * r, 1e-5f);
    float scale = 127.0f / cmax;
    if (tid == 0) inv[m] = cmax / 127.0f;

    char4* qrow = (char4*)(q + (size_t)m * rowlen);
    ushort4* brow = (ushort4*)(qb + (size_t)m * rowlen);
#pragma unroll
    for (int j = 0; j < VE / 4; j++) {
        int qx = __float2int_rn(v[j].x * r * scale);
        int qy = __float2int_rn(v[j].y * r * scale);
        int qz = __float2int_rn(v[j].z * r * scale);
        int qw = __float2int_rn(v[j].w * r * scale);
        qx = min(max(qx, -128), 127); qy = min(max(qy, -128), 127);
        qz = min(max(qz, -128), 127); qw = min(max(qw, -128), 127);
        char4 o8;
        o8.x = (signed char)qx; o8.y = (signed char)qy;
        o8.z = (signed char)qz; o8.w = (signed char)qw;
        qrow[tid + j * 256] = o8;
        ushort4 ob;
        ob.x = __bfloat16_as_ushort(__float2bfloat16_rn((float)qx));
        ob.y = __bfloat16_as_ushort(__float2bfloat16_rn((float)qy));
        ob.z = __bfloat16_as_ushort(__float2bfloat16_rn((float)qz));
        ob.w = __bfloat16_as_ushort(__float2bfloat16_rn((float)qw));
        brow[tid + j * 256] = ob;
    }
}

// ---------------- shared helpers ----------------
__device__ __forceinline__ uint32_t smem_u32(const void* p) {
    uint32_t a;
    asm("{ .reg .u64 t; cvta.to.shared.u64 t, %1; cvt.u32.u64 %0, t; }" : "=r"(a) : "l"(p));
    return a;
}
__device__ __forceinline__ void cp16(uint32_t sdst, const void* gsrc) {
    asm volatile("cp.async.cg.shared.global [%0], [%1], 16;\n" :: "r"(sdst), "l"(gsrc) : "memory");
}
__device__ __forceinline__ void cp_commit() { asm volatile("cp.async.commit_group;\n" ::: "memory"); }
__device__ __forceinline__ void cp_wait0()  { asm volatile("cp.async.wait_group 0;\n" ::: "memory"); }
__device__ __forceinline__ void cp_wait1()  { asm volatile("cp.async.wait_group 1;\n" ::: "memory"); }
__device__ __forceinline__ void ldsm4(uint32_t* r, uint32_t addr) {
    asm volatile("ldmatrix.sync.aligned.m8n8.x4.shared.b16 {%0,%1,%2,%3}, [%4];"
        : "=r"(r[0]), "=r"(r[1]), "=r"(r[2]), "=r"(r[3]) : "r"(addr));
}

// ================= IMMA int8 GEMM (m16n8k32.s8, ldmatrix fragments) =================
#define BMi 128
#define BNi 128
#define BKi 64
#define SROWi 80
#define TILEBi (128 * SROWi)
#define NSTGi 3

__device__ __forceinline__ void mma_s8(int* c, const unsigned* a, const unsigned* b) {
    asm volatile(
        "mma.sync.aligned.m16n8k32.row.col.s32.s8.s8.s32 "
        "{%0,%1,%2,%3},{%4,%5,%6,%7},{%8,%9},{%0,%1,%2,%3};\n"
        : "+r"(c[0]), "+r"(c[1]), "+r"(c[2]), "+r"(c[3])
        : "r"(a[0]), "r"(a[1]), "r"(a[2]), "r"(a[3]), "r"(b[0]), "r"(b[1]));
}

template <bool DUAL>
__global__ void __launch_bounds__(256, 1) gemm_i8(
    const int8_t* __restrict__ A, const int8_t* __restrict__ B1, const int8_t* __restrict__ B2,
    int K, const float* __restrict__ invA, int wi1, int wi2,
    float* __restrict__ out, int ldo)
{
    extern __shared__ char smem[];
    const int TB = (DUAL ? 3 : 2) * TILEBi;
    const uint32_t sb = smem_u32(smem);
    int tid = threadIdx.x;
    int m0 = blockIdx.y * BMi, n0 = blockIdx.x * BNi;
    size_t Kb = (size_t)K;
    const char* Ab  = (const char*)A  + (size_t)m0 * Kb;
    const char* B1b = (const char*)B1 + (size_t)n0 * Kb;
    const char* B2b = DUAL ? ((const char*)B2 + (size_t)n0 * Kb) : nullptr;
    int KT = K / BKi;

    auto issue = [&](int kt) {
        uint32_t base = sb + (kt % NSTGi) * TB;
        size_t k0b = (size_t)kt * BKi;
#pragma unroll
        for (int it = 0; it < 2; it++) {
            int c = it * 256 + tid;
            int row = c >> 2;
            int col = (c & 3) * 16;
            uint32_t soff = (uint32_t)(row * SROWi + col);
            cp16(base + soff,              Ab  + (size_t)row * Kb + k0b + col);
            cp16(base + TILEBi + soff,     B1b + (size_t)row * Kb + k0b + col);
            if (DUAL)
                cp16(base + 2 * TILEBi + soff, B2b + (size_t)row * Kb + k0b + col);
        }
        cp_commit();
    };

    int wid = tid >> 5, lane = tid & 31;
    int wm = wid >> 2, wn = wid & 3;
    int g = lane >> 2, t4 = lane & 3;

    uint32_t offA[4];
#pragma unroll
    for (int im = 0; im < 4; im++)
        offA[im] = (uint32_t)((wm * 64 + im * 16 + (lane & 15)) * SROWi + (lane >> 4) * 16);
    uint32_t offB[2];
#pragma unroll
    for (int ib = 0; ib < 2; ib++)
        offB[ib] = (uint32_t)((wn * 32 + ib * 16 + (lane & 7) + ((lane >> 4) & 1) * 8) * SROWi
                              + ((lane >> 3) & 1) * 16);

    int c1[4][4][4] = {};
    int c2[4][4][4] = {};

    issue(0);
    issue(1);
    for (int kt = 0; kt < KT; kt++) {
        if (kt == KT - 1) cp_wait0(); else cp_wait1();
        __syncthreads();
        if (kt + 2 < KT) issue(kt + 2);

        const uint32_t base = sb + (kt % NSTGi) * TB;
        const uint32_t AsmB = base, B1sm = base + TILEBi, B2sm = base + 2 * TILEBi;

#pragma unroll
        for (int ks = 0; ks < 2; ks++) {
            const uint32_t kb = ks * 32;
            uint32_t a[4][4];
#pragma unroll
            for (int im = 0; im < 4; im++) ldsm4(a[im], AsmB + offA[im] + kb);

            uint32_t b1[2][4];
#pragma unroll
            for (int ib = 0; ib < 2; ib++) ldsm4(b1[ib], B1sm + offB[ib] + kb);
#pragma unroll
            for (int ib = 0; ib < 2; ib++)
#pragma unroll
                for (int sub = 0; sub < 2; sub++)
#pragma unroll
                    for (int im = 0; im < 4; im++)
                        mma_s8(c1[im][ib * 2 + sub], a[im], (unsigned*)&b1[ib][sub * 2]);

            if constexpr (DUAL) {
                uint32_t b2[2][4];
#pragma unroll
                for (int ib = 0; ib < 2; ib++) ldsm4(b2[ib], B2sm + offB[ib] + kb);
#pragma unroll
                for (int ib = 0; ib < 2; ib++)
#pragma unroll
                    for (int sub = 0; sub < 2; sub++)
#pragma unroll
                        for (int im = 0; im < 4; im++)
                            mma_s8(c2[im][ib * 2 + sub], a[im], (unsigned*)&b2[ib][sub * 2]);
            }
        }
        __syncthreads();
    }

    float dq1 = g_wdq[wi1];
    float dq2 = DUAL ? g_wdq[wi2] : 0.0f;
#pragma unroll
    for (int im = 0; im < 4; im++) {
#pragma unroll
        for (int h2 = 0; h2 < 2; h2++) {
            int row = m0 + wm * 64 + im * 16 + g + h2 * 8;
            float ia = invA[row];
#pragma unroll
            for (int in = 0; in < 4; in++) {
                int col = n0 + wn * 32 + in * 8 + t4 * 2;
                size_t o = (size_t)row * ldo + col;
                if constexpr (DUAL) {
                    float f1a = (float)c1[im][in][h2 * 2 + 0] * ia * dq1;
                    float f1b = (float)c1[im][in][h2 * 2 + 1] * ia * dq1;
                    float f2a = (float)c2[im][in][h2 * 2 + 0] * ia * dq2;
                    float f2b = (float)c2[im][in][h2 * 2 + 1] * ia * dq2;
                    out[o]     = f1a / (1.0f + expf(-f1a)) * f2a;
                    out[o + 1] = f1b / (1.0f + expf(-f1b)) * f2b;
                } else {
                    out[o]     = (float)c1[im][in][h2 * 2 + 0] * ia * dq1;
                    out[o + 1] = (float)c1[im][in][h2 * 2 + 1] * ia * dq1;
                }
            }
        }
    }
}

// ---------------- verifies (NaN-safe, 4096 points each) ----------------
__global__ void verify1() {
    int p = blockIdx.x * 256 + threadIdx.x;
    int m = (p * 197 + 11) & (M_TOK - 1);
    int n = (p * 389 + 29) & (F_DIM - 1);
    const char4* xr  = (const char4*)(g_xq  + (size_t)m * E_DIM);
    const char4* w1r = (const char4*)(g_w1q + (size_t)n * E_DIM);
    const char4* w2r = (const char4*)(g_w2q + (size_t)n * E_DIM);
    int s1 = 0, s2 = 0;
    for (int k = 0; k < E_DIM / 4; k++) {
        char4 xv = xr[k], a = w1r[k], b = w2r[k];
        s1 += xv.x * a.x + xv.y * a.y + xv.z * a.z + xv.w * a.w;
        s2 += xv.x * b.x + xv.y * b.y + xv.z * b.z + xv.w * b.w;
    }
    float ia = g_inv_sx[m];
    float f1 = (float)s1 * ia * g_wdq[0];
    float f2 = (float)s2 * ia * g_wdq[1];
    float href = f1 / (1.0f + expf(-f1)) * f2;
    float got = g_h[(size_t)m * F_DIM + n];
    int ok = (fabsf(got - href) <= 1e-2f * fmaxf(fabsf(href), 1.0f)) ? 1 : 0;
    if (!ok) atomicOr(&g_flag1, 1);
}

__global__ void verify2(const float* __restrict__ out) {
    int p = blockIdx.x * 256 + threadIdx.x;
    int m = (p * 197 + 11) & (M_TOK - 1);
    int n = (p * 389 + 29) & (E_DIM - 1);
    const char4* hr  = (const char4*)(g_hq  + (size_t)m * F_DIM);
    const char4* w3r = (const char4*)(g_w3q + (size_t)n * F_DIM);
    int s = 0;
    for (int k = 0; k < F_DIM / 4; k++) {
        char4 hv = hr[k], w = w3r[k];
        s += hv.x * w.x + hv.y * w.y + hv.z * w.z + hv.w * w.w;
    }
    float href = (float)s * g_inv_sh[m] * g_wdq[2];
    float got = out[(size_t)m * E_DIM + n];
    int ok = (fabsf(got - href) <= 1e-2f * fmaxf(fabsf(href), 1.0f)) ? 1 : 0;
    if (!ok) atomicOr(&g_flag2, 1);
}

// ================= bf16 fixup GEMM (R4-proven, per-GEMM flag gate) =================
#define BM 128
#define BN 128
#define SROW 144
#define TILEB (128 * SROW)
#define NSTG 3

__device__ __forceinline__ void mma_bf16(float* c, const uint32_t* a, const uint32_t* b) {
    asm volatile(
        "mma.sync.aligned.m16n8k16.row.col.f32.bf16.bf16.f32 "
        "{%0,%1,%2,%3},{%4,%5,%6,%7},{%8,%9},{%0,%1,%2,%3};\n"
        : "+f"(c[0]), "+f"(c[1]), "+f"(c[2]), "+f"(c[3])
        : "r"(a[0]), "r"(a[1]), "r"(a[2]), "r"(a[3]), "r"(b[0]), "r"(b[1]));
}

template <bool DUAL>
__global__ void __launch_bounds__(256, 1) gemm_bf(
    const __nv_bfloat16* __restrict__ A,
    const __nv_bfloat16* __restrict__ B1,
    const __nv_bfloat16* __restrict__ B2,
    int K, const float* __restrict__ invA, int wi1, int wi2,
    float* __restrict__ out, int ldo)
{
    const volatile int* fl = DUAL ? (volatile int*)&g_flag1 : (volatile int*)&g_flag2;
    if (*fl == 0) return;

    extern __shared__ char smem[];
    const int TB = (DUAL ? 3 : 2) * TILEB;
    const uint32_t sb = smem_u32(smem);
    int tid = threadIdx.x;
    int m0 = blockIdx.y * BM, n0 = blockIdx.x * BN;
    size_t Kb = (size_t)K * 2;
    const char* Ab  = (const char*)A  + (size_t)m0 * Kb;
    const char* B1b = (const char*)B1 + (size_t)n0 * Kb;
    const char* B2b = DUAL ? ((const char*)B2 + (size_t)n0 * Kb) : nullptr;
    int KT = K / 64;

    auto issue = [&](int kt) {
        uint32_t base = sb + (kt % NSTG) * TB;
        size_t k0b = (size_t)kt * 128;
#pragma unroll
        for (int it = 0; it < 4; it++) {
            int c = it * 256 + tid;
            int row = c >> 3;
            int col = (c & 7) * 16;
            uint32_t soff = (uint32_t)(row * SROW + col);
            cp16(base + soff,             Ab  + (size_t)row * Kb + k0b + col);
            cp16(base + TILEB + soff,     B1b + (size_t)row * Kb + k0b + col);
            if (DUAL)
                cp16(base + 2 * TILEB + soff, B2b + (size_t)row * Kb + k0b + col);
        }
        cp_commit();
    };

    int wid = tid >> 5, lane = tid & 31;
    int wm = wid >> 2, wn = wid & 3;
    int g = lane >> 2, t4 = lane & 3;

    uint32_t offA[4];
#pragma unroll
    for (int im = 0; im < 4; im++)
        offA[im] = (uint32_t)((wm * 64 + im * 16 + (lane & 15)) * SROW + (lane >> 4) * 16);
    uint32_t offB[2];
#pragma unroll
    for (int ib = 0; ib < 2; ib++)
        offB[ib] = (uint32_t)((wn * 32 + ib * 16 + (lane & 7) + ((lane >> 4) & 1) * 8) * SROW
                              + ((lane >> 3) & 1) * 16);

    float c1[4][4][4] = {};
    float c2[4][4][4] = {};

    issue(0);
    issue(1);
    for (int kt = 0; kt < KT; kt++) {
        if (kt == KT - 1) cp_wait0(); else cp_wait1();
        __syncthreads();
        if (kt + 2 < KT) issue(kt + 2);

        const uint32_t base = sb + (kt % NSTG) * TB;
        const uint32_t AsmB = base, B1sm = base + TILEB, B2sm = base + 2 * TILEB;

#pragma unroll
        for (int ks = 0; ks < 4; ks++) {
            const uint32_t kb = ks * 32;
            uint32_t a[4][4];
#pragma unroll
            for (int im = 0; im < 4; im++) ldsm4(a[im], AsmB + offA[im] + kb);

            uint32_t b1[2][4];
#pragma unroll
            for (int ib = 0; ib < 2; ib++) ldsm4(b1[ib], B1sm + offB[ib] + kb);
#pragma unroll
            for (int ib = 0; ib < 2; ib++)
#pragma unroll
                for (int sub = 0; sub < 2; sub++)
#pragma unroll
                    for (int im = 0; im < 4; im++)
                        mma_bf16(c1[im][ib * 2 + sub], a[im], &b1[ib][sub * 2]);

            if constexpr (DUAL) {
                uint32_t b2[2][4];
#pragma unroll
                for (int ib = 0; ib < 2; ib++) ldsm4(b2[ib], B2sm + offB[ib] + kb);
#pragma unroll
                for (int ib = 0; ib < 2; ib++)
#pragma unroll
                    for (int sub = 0; sub < 2; sub++)
#pragma unroll
                        for (int im = 0; im < 4; im++)
                            mma_bf16(c2[im][ib * 2 + sub], a[im], &b2[ib][sub * 2]);
            }
        }
        __syncthreads();
    }

    float dq1 = g_wdq[wi1];
    float dq2 = DUAL ? g_wdq[wi2] : 0.0f;
#pragma unroll
    for (int im = 0; im < 4; im++) {
#pragma unroll
        for (int h2 = 0; h2 < 2; h2++) {
            int row = m0 + wm * 64 + im * 16 + g + h2 * 8;
            float ia = invA[row];
#pragma unroll
            for (int in = 0; in < 4; in++) {
                int col = n0 + wn * 32 + in * 8 + t4 * 2;
                size_t o = (size_t)row * ldo + col;
                if constexpr (DUAL) {
                    float f1a = c1[im][in][h2 * 2 + 0] * ia * dq1;
                    float f1b = c1[im][in][h2 * 2 + 1] * ia * dq1;
                    float f2a = c2[im][in][h2 * 2 + 0] * ia * dq2;
                    float f2b = c2[im][in][h2 * 2 + 1] * ia * dq2;
                    out[o]     = f1a / (1.0f + expf(-f1a)) * f2a;
                    out[o + 1] = f1b / (1.0f + expf(-f1b)) * f2b;
                } else {
                    out[o]     = c1[im][in][h2 * 2 + 0] * ia * dq1;
                    out[o + 1] = c1[im][in][h2 * 2 + 1] * ia * dq1;
                }
            }
        }
    }
}

// ---------------- launch ----------------
extern "C" void kernel_launch(void* const* d_in, const int* in_sizes, int n_in,
                              void* d_out, int out_size) {
    const float* x  = (const float*)d_in[0];
    const float* w1 = (const float*)d_in[1];
    const float* w2 = (const float*)d_in[2];
    const float* w3 = (const float*)d_in[3];
    float* out = (float*)d_out;

    void *p_w1b, *p_w2b, *p_w3b, *p_xb, *p_hb;
    void *p_w1q, *p_w2q, *p_w3q, *p_xq, *p_hq, *p_h, *p_isx, *p_ish;
    cudaGetSymbolAddress(&p_w1b, g_w1b);
    cudaGetSymbolAddress(&p_w2b, g_w2b);
    cudaGetSymbolAddress(&p_w3b, g_w3b);
    cudaGetSymbolAddress(&p_xb,  g_xb);
    cudaGetSymbolAddress(&p_hb,  g_hb);
    cudaGetSymbolAddress(&p_w1q, g_w1q);
    cudaGetSymbolAddress(&p_w2q, g_w2q);
    cudaGetSymbolAddress(&p_w3q, g_w3q);
    cudaGetSymbolAddress(&p_xq,  g_xq);
    cudaGetSymbolAddress(&p_hq,  g_hq);
    cudaGetSymbolAddress(&p_h,   g_h);
    cudaGetSymbolAddress(&p_isx, g_inv_sx);
    cudaGetSymbolAddress(&p_ish, g_inv_sh);

    const int SM1i = NSTGi * 3 * TILEBi;
    const int SM2i = NSTGi * 2 * TILEBi;
    const int SM1  = NSTG * 3 * TILEB;
    const int SM2  = NSTG * 2 * TILEB;
    cudaFuncSetAttribute(gemm_i8<true>,  cudaFuncAttributeMaxDynamicSharedMemorySize, SM1i);
    cudaFuncSetAttribute(gemm_i8<false>, cudaFuncAttributeMaxDynamicSharedMemorySize, SM2i);
    cudaFuncSetAttribute(gemm_bf<true>,  cudaFuncAttributeMaxDynamicSharedMemorySize, SM1);
    cudaFuncSetAttribute(gemm_bf<false>, cudaFuncAttributeMaxDynamicSharedMemorySize, SM2);

    // 1) weight scales + flag reset
    wabs_partial<<<256, 256>>>(w1, NW, 0);
    wabs_partial<<<256, 256>>>(w2, NW, 1);
    wabs_partial<<<256, 256>>>(w3, NW, 2);
    wscale_final<<<1, 256>>>();
    reset_flags<<<1, 1>>>();

    // 2) ternary weight quant (signed-safe int8 + bf16)
    quant_w<<<NW / 1024, 256>>>(w1, (int8_t*)p_w1q, (__nv_bfloat16*)p_w1b, NW, 0);
    quant_w<<<NW / 1024, 256>>>(w2, (int8_t*)p_w2q, (__nv_bfloat16*)p_w2b, NW, 1);
    quant_w<<<NW / 1024, 256>>>(w3, (int8_t*)p_w3q, (__nv_bfloat16*)p_w3b, NW, 2);

    // 3) rmsnorm + int8 quant of x
    act_quant<8><<<M_TOK, 256>>>(x, (int8_t*)p_xq, (__nv_bfloat16*)p_xb, (float*)p_isx, E_DIM);

    // 4) IMMA dual GEMM1 + SwiGLU -> g_h
    gemm_i8<true><<<dim3(F_DIM / BNi, M_TOK / BMi), 256, SM1i>>>(
        (const int8_t*)p_xq, (const int8_t*)p_w1q, (const int8_t*)p_w2q,
        E_DIM, (const float*)p_isx, 0, 1, (float*)p_h, F_DIM);

    // 5) verify GEMM1 -> g_flag1
    verify1<<<16, 256>>>();

    // 6) bf16 fixup GEMM1 (only if flag1)
    gemm_bf<true><<<dim3(F_DIM / BN, M_TOK / BM), 256, SM1>>>(
        (const __nv_bfloat16*)p_xb, (const __nv_bfloat16*)p_w1b, (const __nv_bfloat16*)p_w2b,
        E_DIM, (const float*)p_isx, 0, 1, (float*)p_h, F_DIM);

    // 7) rmsnorm + int8 quant of h
    act_quant<32><<<M_TOK, 256>>>((const float*)p_h, (int8_t*)p_hq, (__nv_bfloat16*)p_hb,
                                  (float*)p_ish, F_DIM);

    // 8) IMMA GEMM2 -> out
    gemm_i8<false><<<dim3(E_DIM / BNi, M_TOK / BMi), 256, SM2i>>>(
        (const int8_t*)p_hq, (const int8_t*)p_w3q, nullptr,
        F_DIM, (const float*)p_ish, 2, 2, out, E_DIM);

    // 9) verify GEMM2 -> g_flag2
    verify2<<<16, 256>>>(out);

    // 10) bf16 fixup GEMM2 (only if flag2)
    gemm_bf<false><<<dim3(E_DIM / BN, M_TOK / BM), 256, SM2>>>(
        (const __nv_bfloat16*)p_hb, (const __nv_bfloat16*)p_w3b, nullptr,
        F_DIM, (const float*)p_ish, 2, 2, out, E_DIM);
}

// round 10
// speedup vs baseline: 2.4785x; 2.4785x over previous
#include <cuda_runtime.h>
#include <cuda_bf16.h>
#include <cstdint>
#include <math.h>

#define M_TOK 8192
#define E_DIM 2048
#define F_DIM 8192
#define NW    16777216

// ---------------- device scratch ----------------
__device__ __nv_bfloat16 g_w1b[(size_t)F_DIM * E_DIM];
__device__ __nv_bfloat16 g_w2b[(size_t)F_DIM * E_DIM];
__device__ __nv_bfloat16 g_w3b[(size_t)E_DIM * F_DIM];
__device__ __nv_bfloat16 g_xb [(size_t)M_TOK * E_DIM];
__device__ __nv_bfloat16 g_hb [(size_t)M_TOK * F_DIM];
__device__ float  g_h  [(size_t)M_TOK * F_DIM];
__device__ float  g_inv_sx[M_TOK];
__device__ float  g_inv_sh[M_TOK];
__device__ double g_wpart[3 * 256];
__device__ float  g_wdq[3];
__device__ float  g_wsc[3];

// ---------------- weight absmean: one fused launch (blockIdx.y = slot) ----------------
__global__ void wabs_partial3(const float* __restrict__ w0, const float* __restrict__ w1,
                              const float* __restrict__ w2) {
    const float* w = (blockIdx.y == 0) ? w0 : (blockIdx.y == 1) ? w1 : w2;
    __shared__ double sd[256];
    int tid = threadIdx.x;
    double acc = 0.0;
    for (int i = blockIdx.x * 256 + tid; i < NW; i += 256 * gridDim.x)
        acc += (double)fabsf(w[i]);
    sd[tid] = acc; __syncthreads();
    for (int s = 128; s > 0; s >>= 1) {
        if (tid < s) sd[tid] += sd[tid + s];
        __syncthreads();
    }
    if (tid == 0) g_wpart[blockIdx.y * 256 + blockIdx.x] = sd[0];
}

__global__ void wscale_final() {
    __shared__ double sd[256];
    int tid = threadIdx.x;
    for (int wsel = 0; wsel < 3; wsel++) {
        sd[tid] = g_wpart[wsel * 256 + tid]; __syncthreads();
        for (int s = 128; s > 0; s >>= 1) {
            if (tid < s) sd[tid] += sd[tid + s];
            __syncthreads();
        }
        if (tid == 0) {
            float mean = (float)(sd[0] / (double)NW);
            float dq = fmaxf(mean, 1e-5f);
            g_wdq[wsel] = dq;
            g_wsc[wsel] = 1.0f / dq;
        }
        __syncthreads();
    }
}

// ternary weight quant -> bf16 {-1,0,1}
__global__ void quant_w(const float* __restrict__ w, __nv_bfloat16* __restrict__ q, int wi) {
    float s = g_wsc[wi];
    int i = (blockIdx.x * blockDim.x + threadIdx.x) * 4;
    if (i < NW) {
        float4 v = *(const float4*)(w + i);
        ushort4 o;
        o.x = __bfloat16_as_ushort(__float2bfloat16_rn(fminf(fmaxf(rintf(v.x * s), -1.0f), 1.0f)));
        o.y = __bfloat16_as_ushort(__float2bfloat16_rn(fminf(fmaxf(rintf(v.y * s), -1.0f), 1.0f)));
        o.z = __bfloat16_as_ushort(__float2bfloat16_rn(fminf(fmaxf(rintf(v.z * s), -1.0f), 1.0f)));
        o.w = __bfloat16_as_ushort(__float2bfloat16_rn(fminf(fmaxf(rintf(v.w * s), -1.0f), 1.0f)));
        *(ushort4*)(q + i) = o;
    }
}

// rmsnorm + absmax int8-grid quant (stored as exact integers in bf16)
template <int VE>
__global__ void act_quant(const float* __restrict__ in, __nv_bfloat16* __restrict__ q,
                          float* __restrict__ inv, int rowlen) {
    int m = blockIdx.x, tid = threadIdx.x;
    const float4* row = (const float4*)(in + (size_t)m * rowlen);
    float4 v[VE / 4];
    float ss = 0.0f, mx = 0.0f;
#pragma unroll
    for (int j = 0; j < VE / 4; j++) {
        v[j] = row[tid + j * 256];
        ss += v[j].x * v[j].x + v[j].y * v[j].y + v[j].z * v[j].z + v[j].w * v[j].w;
        mx = fmaxf(mx, fmaxf(fmaxf(fabsf(v[j].x), fabsf(v[j].y)),
                             fmaxf(fabsf(v[j].z), fabsf(v[j].w))));
    }
    __shared__ float sss[256], smx[256];
    sss[tid] = ss; smx[tid] = mx; __syncthreads();
    for (int s = 128; s > 0; s >>= 1) {
        if (tid < s) {
            sss[tid] += sss[tid + s];
            smx[tid] = fmaxf(smx[tid], smx[tid + s]);
        }
        __syncthreads();
    }
    float r = rsqrtf(sss[0] / (float)rowlen + 1e-6f);
    float cmax = fmaxf(smx[0] * r, 1e-5f);
    float scale = 127.0f / cmax;
    if (tid == 0) inv[m] = cmax / 127.0f;

    ushort4* qrow = (ushort4*)(q + (size_t)m * rowlen);
#pragma unroll
    for (int j = 0; j < VE / 4; j++) {
        int qx = __float2int_rn(v[j].x * r * scale);
        int qy = __float2int_rn(v[j].y * r * scale);
        int qz = __float2int_rn(v[j].z * r * scale);
        int qw = __float2int_rn(v[j].w * r * scale);
        qx = min(max(qx, -128), 127); qy = min(max(qy, -128), 127);
        qz = min(max(qz, -128), 127); qw = min(max(qw, -128), 127);
        ushort4 o;
        o.x = __bfloat16_as_ushort(__float2bfloat16_rn((float)qx));
        o.y = __bfloat16_as_ushort(__float2bfloat16_rn((float)qy));
        o.z = __bfloat16_as_ushort(__float2bfloat16_rn((float)qz));
        o.w = __bfloat16_as_ushort(__float2bfloat16_rn((float)qw));
        qrow[tid + j * 256] = o;
    }
}

// ---------------- bf16 mma.sync GEMM: ldmatrix + 3-stage cp.async, 1 sync/iter ----------------
#define BM 128
#define BN 128
#define SROW 144
#define TILEB (128 * SROW)
#define NSTG 3

__device__ __forceinline__ uint32_t smem_u32(const void* p) {
    uint32_t a;
    asm("{ .reg .u64 t; cvta.to.shared.u64 t, %1; cvt.u32.u64 %0, t; }" : "=r"(a) : "l"(p));
    return a;
}
__device__ __forceinline__ void cp16(uint32_t sdst, const void* gsrc) {
    asm volatile("cp.async.cg.shared.global [%0], [%1], 16;\n" :: "r"(sdst), "l"(gsrc) : "memory");
}
__device__ __forceinline__ void cp_commit() { asm volatile("cp.async.commit_group;\n" ::: "memory"); }
__device__ __forceinline__ void cp_wait0()  { asm volatile("cp.async.wait_group 0;\n" ::: "memory"); }
__device__ __forceinline__ void cp_wait1()  { asm volatile("cp.async.wait_group 1;\n" ::: "memory"); }
__device__ __forceinline__ void ldsm4(uint32_t* r, uint32_t addr) {
    asm volatile("ldmatrix.sync.aligned.m8n8.x4.shared.b16 {%0,%1,%2,%3}, [%4];"
        : "=r"(r[0]), "=r"(r[1]), "=r"(r[2]), "=r"(r[3]) : "r"(addr));
}
__device__ __forceinline__ void mma_bf16(float* c, const uint32_t* a, const uint32_t* b) {
    asm volatile(
        "mma.sync.aligned.m16n8k16.row.col.f32.bf16.bf16.f32 "
        "{%0,%1,%2,%3},{%4,%5,%6,%7},{%8,%9},{%0,%1,%2,%3};\n"
        : "+f"(c[0]), "+f"(c[1]), "+f"(c[2]), "+f"(c[3])
        : "r"(a[0]), "r"(a[1]), "r"(a[2]), "r"(a[3]), "r"(b[0]), "r"(b[1]));
}

template <bool DUAL>
__global__ void __launch_bounds__(256, 1) gemm_bf(
    const __nv_bfloat16* __restrict__ A,
    const __nv_bfloat16* __restrict__ B1,
    const __nv_bfloat16* __restrict__ B2,
    int K, const float* __restrict__ invA, int wi1, int wi2,
    float* __restrict__ out, int ldo)
{
    extern __shared__ char smem[];
    const int TB = (DUAL ? 3 : 2) * TILEB;
    const uint32_t sb = smem_u32(smem);
    int tid = threadIdx.x;
    int m0 = blockIdx.y * BM, n0 = blockIdx.x * BN;
    size_t Kb = (size_t)K * 2;
    const char* Ab  = (const char*)A  + (size_t)m0 * Kb;
    const char* B1b = (const char*)B1 + (size_t)n0 * Kb;
    const char* B2b = DUAL ? ((const char*)B2 + (size_t)n0 * Kb) : nullptr;
    int KT = K / 64;

    auto issue = [&](int kt) {
        uint32_t base = sb + (kt % NSTG) * TB;
        size_t k0b = (size_t)kt * 128;
#pragma unroll
        for (int it = 0; it < 4; it++) {
            int c = it * 256 + tid;
            int row = c >> 3;
            int col = (c & 7) * 16;
            uint32_t soff = (uint32_t)(row * SROW + col);
            cp16(base + soff,             Ab  + (size_t)row * Kb + k0b + col);
            cp16(base + TILEB + soff,     B1b + (size_t)row * Kb + k0b + col);
            if (DUAL)
                cp16(base + 2 * TILEB + soff, B2b + (size_t)row * Kb + k0b + col);
        }
        cp_commit();
    };

    int wid = tid >> 5, lane = tid & 31;
    int wm = wid >> 2, wn = wid & 3;     // 2 (M) x 4 (N) warps; warp tile 64x32
    int g = lane >> 2, t4 = lane & 3;

    uint32_t offA[4];
#pragma unroll
    for (int im = 0; im < 4; im++)
        offA[im] = (uint32_t)((wm * 64 + im * 16 + (lane & 15)) * SROW + (lane >> 4) * 16);
    uint32_t offB[2];
#pragma unroll
    for (int ib = 0; ib < 2; ib++)
        offB[ib] = (uint32_t)((wn * 32 + ib * 16 + (lane & 7) + ((lane >> 4) & 1) * 8) * SROW
                              + ((lane >> 3) & 1) * 16);

    float c1[4][4][4] = {};
    float c2[4][4][4] = {};

    issue(0);
    issue(1);
    for (int kt = 0; kt < KT; kt++) {
        if (kt == KT - 1) cp_wait0(); else cp_wait1();
        __syncthreads();                      // single barrier per k-tile
        if (kt + 2 < KT) issue(kt + 2);       // writes stage (kt+2)%3 — never read this iter

        const uint32_t base = sb + (kt % NSTG) * TB;
        const uint32_t AsmB = base, B1sm = base + TILEB, B2sm = base + 2 * TILEB;

#pragma unroll
        for (int ks = 0; ks < 4; ks++) {
            const uint32_t kb = ks * 32;
            uint32_t a[4][4];
#pragma unroll
            for (int im = 0; im < 4; im++) ldsm4(a[im], AsmB + offA[im] + kb);

            uint32_t b1[2][4];
#pragma unroll
            for (int ib = 0; ib < 2; ib++) ldsm4(b1[ib], B1sm + offB[ib] + kb);
#pragma unroll
            for (int ib = 0; ib < 2; ib++)
#pragma unroll
                for (int sub = 0; sub < 2; sub++)
#pragma unroll
                    for (int im = 0; im < 4; im++)
                        mma_bf16(c1[im][ib * 2 + sub], a[im], &b1[ib][sub * 2]);

            if constexpr (DUAL) {
                uint32_t b2[2][4];
#pragma unroll
                for (int ib = 0; ib < 2; ib++) ldsm4(b2[ib], B2sm + offB[ib] + kb);
#pragma unroll
                for (int ib = 0; ib < 2; ib++)
#pragma unroll
                    for (int sub = 0; sub < 2; sub++)
#pragma unroll
                        for (int im = 0; im < 4; im++)
                            mma_bf16(c2[im][ib * 2 + sub], a[im], &b2[ib][sub * 2]);
            }
        }
    }

    // epilogue: dequant (+ SwiGLU for DUAL). Accumulators are exact integers.
    float dq1 = g_wdq[wi1];
    float dq2 = DUAL ? g_wdq[wi2] : 0.0f;
#pragma unroll
    for (int im = 0; im < 4; im++) {
#pragma unroll
        for (int h2 = 0; h2 < 2; h2++) {
            int row = m0 + wm * 64 + im * 16 + g + h2 * 8;
            float ia = invA[row];
#pragma unroll
            for (int in = 0; in < 4; in++) {
                int col = n0 + wn * 32 + in * 8 + t4 * 2;
                size_t o = (size_t)row * ldo + col;
                if constexpr (DUAL) {
                    float f1a = c1[im][in][h2 * 2 + 0] * ia * dq1;
                    float f1b = c1[im][in][h2 * 2 + 1] * ia * dq1;
                    float f2a = c2[im][in][h2 * 2 + 0] * ia * dq2;
                    float f2b = c2[im][in][h2 * 2 + 1] * ia * dq2;
                    out[o]     = f1a / (1.0f + expf(-f1a)) * f2a;
                    out[o + 1] = f1b / (1.0f + expf(-f1b)) * f2b;
                } else {
                    out[o]     = c1[im][in][h2 * 2 + 0] * ia * dq1;
                    out[o + 1] = c1[im][in][h2 * 2 + 1] * ia * dq1;
                }
            }
        }
    }
}

// ---------------- launch ----------------
extern "C" void kernel_launch(void* const* d_in, const int* in_sizes, int n_in,
                              void* d_out, int out_size) {
    const float* x  = (const float*)d_in[0];
    const float* w1 = (const float*)d_in[1];
    const float* w2 = (const float*)d_in[2];
    const float* w3 = (const float*)d_in[3];
    float* out = (float*)d_out;

    void *p_w1b, *p_w2b, *p_w3b, *p_xb, *p_hb, *p_h, *p_isx, *p_ish;
    cudaGetSymbolAddress(&p_w1b, g_w1b);
    cudaGetSymbolAddress(&p_w2b, g_w2b);
    cudaGetSymbolAddress(&p_w3b, g_w3b);
    cudaGetSymbolAddress(&p_xb,  g_xb);
    cudaGetSymbolAddress(&p_hb,  g_hb);
    cudaGetSymbolAddress(&p_h,   g_h);
    cudaGetSymbolAddress(&p_isx, g_inv_sx);
    cudaGetSymbolAddress(&p_ish, g_inv_sh);

    const int SM1 = NSTG * 3 * TILEB;   // 162 KB (dual)
    const int SM2 = NSTG * 2 * TILEB;   // 108 KB (single)
    cudaFuncSetAttribute(gemm_bf<true>,  cudaFuncAttributeMaxDynamicSharedMemorySize, SM1);
    cudaFuncSetAttribute(gemm_bf<false>, cudaFuncAttributeMaxDynamicSharedMemorySize, SM2);

    // 1) weight scales (one fused partial pass + final)
    wabs_partial3<<<dim3(256, 3), 256>>>(w1, w2, w3);
    wscale_final<<<1, 256>>>();

    // 2) ternary weight quantization (bf16 {-1,0,1})
    quant_w<<<NW / 1024, 256>>>(w1, (__nv_bfloat16*)p_w1b, 0);
    quant_w<<<NW / 1024, 256>>>(w2, (__nv_bfloat16*)p_w2b, 1);
    quant_w<<<NW / 1024, 256>>>(w3, (__nv_bfloat16*)p_w3b, 2);

    // 3) rmsnorm + int8-grid quant of x
    act_quant<8><<<M_TOK, 256>>>(x, (__nv_bfloat16*)p_xb, (float*)p_isx, E_DIM);

    // 4) fused dual GEMM1 (w1,w2) + SwiGLU -> h (fp32)
    gemm_bf<true><<<dim3(F_DIM / BN, M_TOK / BM), 256, SM1>>>(
        (const __nv_bfloat16*)p_xb, (const __nv_bfloat16*)p_w1b, (const __nv_bfloat16*)p_w2b,
        E_DIM, (const float*)p_isx, 0, 1, (float*)p_h, F_DIM);

    // 5) rmsnorm + int8-grid quant of h
    act_quant<32><<<M_TOK, 256>>>((const float*)p_h, (__nv_bfloat16*)p_hb, (float*)p_ish, F_DIM);

    // 6) GEMM2 (w3) -> out
    gemm_bf<false><<<dim3(E_DIM / BN, M_TOK / BM), 256, SM2>>>(
        (const __nv_bfloat16*)p_hb, (const __nv_bfloat16*)p_w3b, nullptr,
        F_DIM, (const float*)p_ish, 2, 2, out, E_DIM);
}

// round 11
// speedup vs baseline: 2.5325x; 1.0218x over previous
#include <cuda_runtime.h>
#include <cuda_bf16.h>
#include <cstdint>
#include <math.h>

#define M_TOK 8192
#define E_DIM 2048
#define F_DIM 8192
#define NW    16777216

// ---------------- device scratch ----------------
__device__ __nv_bfloat16 g_w1b[(size_t)F_DIM * E_DIM];
__device__ __nv_bfloat16 g_w2b[(size_t)F_DIM * E_DIM];
__device__ __nv_bfloat16 g_w3b[(size_t)E_DIM * F_DIM];
__device__ __nv_bfloat16 g_xb [(size_t)M_TOK * E_DIM];
__device__ __nv_bfloat16 g_hb [(size_t)M_TOK * F_DIM];
__device__ float  g_h  [(size_t)M_TOK * F_DIM];
__device__ float  g_inv_sx[M_TOK];
__device__ float  g_inv_sh[M_TOK];
__device__ double g_wpart[3 * 256];
__device__ float  g_wdq[3];
__device__ float  g_wsc[3];

// ---------------- weight absmean: one fused launch (blockIdx.y = slot) ----------------
__global__ void wabs_partial3(const float* __restrict__ w0, const float* __restrict__ w1,
                              const float* __restrict__ w2) {
    const float* w = (blockIdx.y == 0) ? w0 : (blockIdx.y == 1) ? w1 : w2;
    __shared__ double sd[256];
    int tid = threadIdx.x;
    double acc = 0.0;
    for (int i = blockIdx.x * 256 + tid; i < NW; i += 256 * gridDim.x)
        acc += (double)fabsf(w[i]);
    sd[tid] = acc; __syncthreads();
    for (int s = 128; s > 0; s >>= 1) {
        if (tid < s) sd[tid] += sd[tid + s];
        __syncthreads();
    }
    if (tid == 0) g_wpart[blockIdx.y * 256 + blockIdx.x] = sd[0];
}

__global__ void wscale_final() {
    __shared__ double sd[256];
    int tid = threadIdx.x;
    for (int wsel = 0; wsel < 3; wsel++) {
        sd[tid] = g_wpart[wsel * 256 + tid]; __syncthreads();
        for (int s = 128; s > 0; s >>= 1) {
            if (tid < s) sd[tid] += sd[tid + s];
            __syncthreads();
        }
        if (tid == 0) {
            float mean = (float)(sd[0] / (double)NW);
            float dq = fmaxf(mean, 1e-5f);
            g_wdq[wsel] = dq;
            g_wsc[wsel] = 1.0f / dq;
        }
        __syncthreads();
    }
}

// ternary weight quant -> bf16 {-1,0,1}; one launch for all 3 weights (blockIdx.y)
__global__ void quant_w3(const float* __restrict__ w0, const float* __restrict__ w1,
                         const float* __restrict__ w2,
                         __nv_bfloat16* __restrict__ q0, __nv_bfloat16* __restrict__ q1,
                         __nv_bfloat16* __restrict__ q2) {
    int wi = blockIdx.y;
    const float* w = (wi == 0) ? w0 : (wi == 1) ? w1 : w2;
    __nv_bfloat16* q = (wi == 0) ? q0 : (wi == 1) ? q1 : q2;
    float s = g_wsc[wi];
    int i = (blockIdx.x * blockDim.x + threadIdx.x) * 4;
    if (i < NW) {
        float4 v = *(const float4*)(w + i);
        ushort4 o;
        o.x = __bfloat16_as_ushort(__float2bfloat16_rn(fminf(fmaxf(rintf(v.x * s), -1.0f), 1.0f)));
        o.y = __bfloat16_as_ushort(__float2bfloat16_rn(fminf(fmaxf(rintf(v.y * s), -1.0f), 1.0f)));
        o.z = __bfloat16_as_ushort(__float2bfloat16_rn(fminf(fmaxf(rintf(v.z * s), -1.0f), 1.0f)));
        o.w = __bfloat16_as_ushort(__float2bfloat16_rn(fminf(fmaxf(rintf(v.w * s), -1.0f), 1.0f)));
        *(ushort4*)(q + i) = o;
    }
}

// rmsnorm + absmax int8-grid quant (stored as exact integers in bf16)
template <int VE>
__global__ void act_quant(const float* __restrict__ in, __nv_bfloat16* __restrict__ q,
                          float* __restrict__ inv, int rowlen) {
    int m = blockIdx.x, tid = threadIdx.x;
    const float4* row = (const float4*)(in + (size_t)m * rowlen);
    float4 v[VE / 4];
    float ss = 0.0f, mx = 0.0f;
#pragma unroll
    for (int j = 0; j < VE / 4; j++) {
        v[j] = row[tid + j * 256];
        ss += v[j].x * v[j].x + v[j].y * v[j].y + v[j].z * v[j].z + v[j].w * v[j].w;
        mx = fmaxf(mx, fmaxf(fmaxf(fabsf(v[j].x), fabsf(v[j].y)),
                             fmaxf(fabsf(v[j].z), fabsf(v[j].w))));
    }
    __shared__ float sss[256], smx[256];
    sss[tid] = ss; smx[tid] = mx; __syncthreads();
    for (int s = 128; s > 0; s >>= 1) {
        if (tid < s) {
            sss[tid] += sss[tid + s];
            smx[tid] = fmaxf(smx[tid], smx[tid + s]);
        }
        __syncthreads();
    }
    float r = rsqrtf(sss[0] / (float)rowlen + 1e-6f);
    float cmax = fmaxf(smx[0] * r, 1e-5f);
    float scale = 127.0f / cmax;
    if (tid == 0) inv[m] = cmax / 127.0f;

    ushort4* qrow = (ushort4*)(q + (size_t)m * rowlen);
#pragma unroll
    for (int j = 0; j < VE / 4; j++) {
        int qx = __float2int_rn(v[j].x * r * scale);
        int qy = __float2int_rn(v[j].y * r * scale);
        int qz = __float2int_rn(v[j].z * r * scale);
        int qw = __float2int_rn(v[j].w * r * scale);
        qx = min(max(qx, -128), 127); qy = min(max(qy, -128), 127);
        qz = min(max(qz, -128), 127); qw = min(max(qw, -128), 127);
        ushort4 o;
        o.x = __bfloat16_as_ushort(__float2bfloat16_rn((float)qx));
        o.y = __bfloat16_as_ushort(__float2bfloat16_rn((float)qy));
        o.z = __bfloat16_as_ushort(__float2bfloat16_rn((float)qz));
        o.w = __bfloat16_as_ushort(__float2bfloat16_rn((float)qw));
        qrow[tid + j * 256] = o;
    }
}

// ---------------- bf16 mma.sync GEMM: ldmatrix + 3-stage cp.async, 1 sync/iter ----------------
#define BM 128
#define BN 128
#define SROW 144
#define TILEB (128 * SROW)
#define NSTG 3

__device__ __forceinline__ uint32_t smem_u32(const void* p) {
    uint32_t a;
    asm("{ .reg .u64 t; cvta.to.shared.u64 t, %1; cvt.u32.u64 %0, t; }" : "=r"(a) : "l"(p));
    return a;
}
__device__ __forceinline__ void cp16(uint32_t sdst, const void* gsrc) {
    asm volatile("cp.async.cg.shared.global [%0], [%1], 16;\n" :: "r"(sdst), "l"(gsrc) : "memory");
}
__device__ __forceinline__ void cp_commit() { asm volatile("cp.async.commit_group;\n" ::: "memory"); }
__device__ __forceinline__ void cp_wait0()  { asm volatile("cp.async.wait_group 0;\n" ::: "memory"); }
__device__ __forceinline__ void cp_wait1()  { asm volatile("cp.async.wait_group 1;\n" ::: "memory"); }
__device__ __forceinline__ void ldsm4(uint32_t* r, uint32_t addr) {
    asm volatile("ldmatrix.sync.aligned.m8n8.x4.shared.b16 {%0,%1,%2,%3}, [%4];"
        : "=r"(r[0]), "=r"(r[1]), "=r"(r[2]), "=r"(r[3]) : "r"(addr));
}
__device__ __forceinline__ void mma_bf16(float* c, const uint32_t* a, const uint32_t* b) {
    asm volatile(
        "mma.sync.aligned.m16n8k16.row.col.f32.bf16.bf16.f32 "
        "{%0,%1,%2,%3},{%4,%5,%6,%7},{%8,%9},{%0,%1,%2,%3};\n"
        : "+f"(c[0]), "+f"(c[1]), "+f"(c[2]), "+f"(c[3])
        : "r"(a[0]), "r"(a[1]), "r"(a[2]), "r"(a[3]), "r"(b[0]), "r"(b[1]));
}

// fast sigmoid-product: silu(a)*b = a*b/(1+e^-a), with MUFU-only exp/div
__device__ __forceinline__ float swiglu_f(float a, float b) {
    return __fdividef(a * b, 1.0f + __expf(-a));
}

template <bool DUAL>
__global__ void __launch_bounds__(256, 1) gemm_bf(
    const __nv_bfloat16* __restrict__ A,
    const __nv_bfloat16* __restrict__ B1,
    const __nv_bfloat16* __restrict__ B2,
    int K, const float* __restrict__ invA, int wi1, int wi2,
    float* __restrict__ out, int ldo)
{
    extern __shared__ char smem[];
    const int TB = (DUAL ? 3 : 2) * TILEB;
    const uint32_t sb = smem_u32(smem);
    int tid = threadIdx.x;
    int m0 = blockIdx.y * BM, n0 = blockIdx.x * BN;
    size_t Kb = (size_t)K * 2;
    const char* Ab  = (const char*)A  + (size_t)m0 * Kb;
    const char* B1b = (const char*)B1 + (size_t)n0 * Kb;
    const char* B2b = DUAL ? ((const char*)B2 + (size_t)n0 * Kb) : nullptr;
    int KT = K / 64;

    auto issue = [&](int kt) {
        uint32_t base = sb + (kt % NSTG) * TB;
        size_t k0b = (size_t)kt * 128;
#pragma unroll
        for (int it = 0; it < 4; it++) {
            int c = it * 256 + tid;
            int row = c >> 3;
            int col = (c & 7) * 16;
            uint32_t soff = (uint32_t)(row * SROW + col);
            cp16(base + soff,             Ab  + (size_t)row * Kb + k0b + col);
            cp16(base + TILEB + soff,     B1b + (size_t)row * Kb + k0b + col);
            if (DUAL)
                cp16(base + 2 * TILEB + soff, B2b + (size_t)row * Kb + k0b + col);
        }
        cp_commit();
    };

    int wid = tid >> 5, lane = tid & 31;
    int wm = wid >> 2, wn = wid & 3;     // 2 (M) x 4 (N) warps; warp tile 64x32
    int g = lane >> 2, t4 = lane & 3;

    uint32_t offA[4];
#pragma unroll
    for (int im = 0; im < 4; im++)
        offA[im] = (uint32_t)((wm * 64 + im * 16 + (lane & 15)) * SROW + (lane >> 4) * 16);
    uint32_t offB[2];
#pragma unroll
    for (int ib = 0; ib < 2; ib++)
        offB[ib] = (uint32_t)((wn * 32 + ib * 16 + (lane & 7) + ((lane >> 4) & 1) * 8) * SROW
                              + ((lane >> 3) & 1) * 16);

    float c1[4][4][4] = {};
    float c2[4][4][4] = {};

    issue(0);
    issue(1);
    for (int kt = 0; kt < KT; kt++) {
        if (kt == KT - 1) cp_wait0(); else cp_wait1();
        __syncthreads();                      // single barrier per k-tile
        if (kt + 2 < KT) issue(kt + 2);       // writes stage (kt+2)%3 — never read this iter

        const uint32_t base = sb + (kt % NSTG) * TB;
        const uint32_t AsmB = base, B1sm = base + TILEB, B2sm = base + 2 * TILEB;

#pragma unroll
        for (int ks = 0; ks < 4; ks++) {
            const uint32_t kb = ks * 32;
            uint32_t a[4][4];
#pragma unroll
            for (int im = 0; im < 4; im++) ldsm4(a[im], AsmB + offA[im] + kb);

            uint32_t b1[2][4];
#pragma unroll
            for (int ib = 0; ib < 2; ib++) ldsm4(b1[ib], B1sm + offB[ib] + kb);
#pragma unroll
            for (int ib = 0; ib < 2; ib++)
#pragma unroll
                for (int sub = 0; sub < 2; sub++)
#pragma unroll
                    for (int im = 0; im < 4; im++)
                        mma_bf16(c1[im][ib * 2 + sub], a[im], &b1[ib][sub * 2]);

            if constexpr (DUAL) {
                uint32_t b2[2][4];
#pragma unroll
                for (int ib = 0; ib < 2; ib++) ldsm4(b2[ib], B2sm + offB[ib] + kb);
#pragma unroll
                for (int ib = 0; ib < 2; ib++)
#pragma unroll
                    for (int sub = 0; sub < 2; sub++)
#pragma unroll
                        for (int im = 0; im < 4; im++)
                            mma_bf16(c2[im][ib * 2 + sub], a[im], &b2[ib][sub * 2]);
            }
        }
    }

    // epilogue: dequant (+ fast SwiGLU for DUAL). Accumulators are exact integers.
    float dq1 = g_wdq[wi1];
    float dq2 = DUAL ? g_wdq[wi2] : 0.0f;
#pragma unroll
    for (int im = 0; im < 4; im++) {
#pragma unroll
        for (int h2 = 0; h2 < 2; h2++) {
            int row = m0 + wm * 64 + im * 16 + g + h2 * 8;
            float ia = invA[row];
            float s1 = ia * dq1, s2 = ia * dq2;
#pragma unroll
            for (int in = 0; in < 4; in++) {
                int col = n0 + wn * 32 + in * 8 + t4 * 2;
                size_t o = (size_t)row * ldo + col;
                if constexpr (DUAL) {
                    float f1a = c1[im][in][h2 * 2 + 0] * s1;
                    float f1b = c1[im][in][h2 * 2 + 1] * s1;
                    float f2a = c2[im][in][h2 * 2 + 0] * s2;
                    float f2b = c2[im][in][h2 * 2 + 1] * s2;
                    out[o]     = swiglu_f(f1a, f2a);
                    out[o + 1] = swiglu_f(f1b, f2b);
                } else {
                    out[o]     = c1[im][in][h2 * 2 + 0] * s1;
                    out[o + 1] = c1[im][in][h2 * 2 + 1] * s1;
                }
            }
        }
    }
}

// ---------------- launch ----------------
extern "C" void kernel_launch(void* const* d_in, const int* in_sizes, int n_in,
                              void* d_out, int out_size) {
    const float* x  = (const float*)d_in[0];
    const float* w1 = (const float*)d_in[1];
    const float* w2 = (const float*)d_in[2];
    const float* w3 = (const float*)d_in[3];
    float* out = (float*)d_out;

    void *p_w1b, *p_w2b, *p_w3b, *p_xb, *p_hb, *p_h, *p_isx, *p_ish;
    cudaGetSymbolAddress(&p_w1b, g_w1b);
    cudaGetSymbolAddress(&p_w2b, g_w2b);
    cudaGetSymbolAddress(&p_w3b, g_w3b);
    cudaGetSymbolAddress(&p_xb,  g_xb);
    cudaGetSymbolAddress(&p_hb,  g_hb);
    cudaGetSymbolAddress(&p_h,   g_h);
    cudaGetSymbolAddress(&p_isx, g_inv_sx);
    cudaGetSymbolAddress(&p_ish, g_inv_sh);

    const int SM1 = NSTG * 3 * TILEB;   // 162 KB (dual)
    const int SM2 = NSTG * 2 * TILEB;   // 108 KB (single)
    cudaFuncSetAttribute(gemm_bf<true>,  cudaFuncAttributeMaxDynamicSharedMemorySize, SM1);
    cudaFuncSetAttribute(gemm_bf<false>, cudaFuncAttributeMaxDynamicSharedMemorySize, SM2);

    // 1) weight scales (fused partial pass + final)
    wabs_partial3<<<dim3(256, 3), 256>>>(w1, w2, w3);
    wscale_final<<<1, 256>>>();

    // 2) ternary weight quantization, one launch for all three
    quant_w3<<<dim3(NW / 1024, 3), 256>>>(w1, w2, w3,
        (__nv_bfloat16*)p_w1b, (__nv_bfloat16*)p_w2b, (__nv_bfloat16*)p_w3b);

    // 3) rmsnorm + int8-grid quant of x
    act_quant<8><<<M_TOK, 256>>>(x, (__nv_bfloat16*)p_xb, (float*)p_isx, E_DIM);

    // 4) fused dual GEMM1 (w1,w2) + SwiGLU -> h (fp32)
    gemm_bf<true><<<dim3(F_DIM / BN, M_TOK / BM), 256, SM1>>>(
        (const __nv_bfloat16*)p_xb, (const __nv_bfloat16*)p_w1b, (const __nv_bfloat16*)p_w2b,
        E_DIM, (const float*)p_isx, 0, 1, (float*)p_h, F_DIM);

    // 5) rmsnorm + int8-grid quant of h
    act_quant<32><<<M_TOK, 256>>>((const float*)p_h, (__nv_bfloat16*)p_hb, (float*)p_ish, F_DIM);

    // 6) GEMM2 (w3) -> out
    gemm_bf<false><<<dim3(E_DIM / BN, M_TOK / BM), 256, SM2>>>(
        (const __nv_bfloat16*)p_hb, (const __nv_bfloat16*)p_w3b, nullptr,
        F_DIM, (const float*)p_ish, 2, 2, out, E_DIM);
}

// round 12
// speedup vs baseline: 2.5550x; 1.0089x over previous
#include <cuda_runtime.h>
#include <cuda_bf16.h>
#include <cstdint>
#include <math.h>

#define M_TOK 8192
#define E_DIM 2048
#define F_DIM 8192
#define NW    16777216

// ---------------- device scratch ----------------
__device__ __nv_bfloat16 g_w1b[(size_t)F_DIM * E_DIM];
__device__ __nv_bfloat16 g_w2b[(size_t)F_DIM * E_DIM];
__device__ __nv_bfloat16 g_w3b[(size_t)E_DIM * F_DIM];
__device__ __nv_bfloat16 g_xb [(size_t)M_TOK * E_DIM];
__device__ __nv_bfloat16 g_hb [(size_t)M_TOK * F_DIM];
__device__ float  g_h  [(size_t)M_TOK * F_DIM];
__device__ float  g_inv_sx[M_TOK];
__device__ float  g_inv_sh[M_TOK];
__device__ double g_wpart[3 * 256];
__device__ float  g_wdq[3];
__device__ float  g_wsc[3];

// ---------------- weight absmean: one fused launch (blockIdx.y = slot) ----------------
__global__ void wabs_partial3(const float* __restrict__ w0, const float* __restrict__ w1,
                              const float* __restrict__ w2) {
    const float* w = (blockIdx.y == 0) ? w0 : (blockIdx.y == 1) ? w1 : w2;
    __shared__ double sd[256];
    int tid = threadIdx.x;
    double acc = 0.0;
    for (int i = blockIdx.x * 256 + tid; i < NW; i += 256 * gridDim.x)
        acc += (double)fabsf(w[i]);
    sd[tid] = acc; __syncthreads();
    for (int s = 128; s > 0; s >>= 1) {
        if (tid < s) sd[tid] += sd[tid + s];
        __syncthreads();
    }
    if (tid == 0) g_wpart[blockIdx.y * 256 + blockIdx.x] = sd[0];
}

__global__ void wscale_final() {
    __shared__ double sd[256];
    int tid = threadIdx.x;
    for (int wsel = 0; wsel < 3; wsel++) {
        sd[tid] = g_wpart[wsel * 256 + tid]; __syncthreads();
        for (int s = 128; s > 0; s >>= 1) {
            if (tid < s) sd[tid] += sd[tid + s];
            __syncthreads();
        }
        if (tid == 0) {
            float mean = (float)(sd[0] / (double)NW);
            float dq = fmaxf(mean, 1e-5f);
            g_wdq[wsel] = dq;
            g_wsc[wsel] = 1.0f / dq;
        }
        __syncthreads();
    }
}

// ternary weight quant -> bf16 {-1,0,1}; one launch for all 3 weights (blockIdx.y)
__global__ void quant_w3(const float* __restrict__ w0, const float* __restrict__ w1,
                         const float* __restrict__ w2,
                         __nv_bfloat16* __restrict__ q0, __nv_bfloat16* __restrict__ q1,
                         __nv_bfloat16* __restrict__ q2) {
    int wi = blockIdx.y;
    const float* w = (wi == 0) ? w0 : (wi == 1) ? w1 : w2;
    __nv_bfloat16* q = (wi == 0) ? q0 : (wi == 1) ? q1 : q2;
    float s = g_wsc[wi];
    int i = (blockIdx.x * blockDim.x + threadIdx.x) * 4;
    if (i < NW) {
        float4 v = *(const float4*)(w + i);
        ushort4 o;
        o.x = __bfloat16_as_ushort(__float2bfloat16_rn(fminf(fmaxf(rintf(v.x * s), -1.0f), 1.0f)));
        o.y = __bfloat16_as_ushort(__float2bfloat16_rn(fminf(fmaxf(rintf(v.y * s), -1.0f), 1.0f)));
        o.z = __bfloat16_as_ushort(__float2bfloat16_rn(fminf(fmaxf(rintf(v.z * s), -1.0f), 1.0f)));
        o.w = __bfloat16_as_ushort(__float2bfloat16_rn(fminf(fmaxf(rintf(v.w * s), -1.0f), 1.0f)));
        *(ushort4*)(q + i) = o;
    }
}

// rmsnorm + absmax int8-grid quant (stored as exact integers in bf16)
template <int VE>
__global__ void act_quant(const float* __restrict__ in, __nv_bfloat16* __restrict__ q,
                          float* __restrict__ inv, int rowlen) {
    int m = blockIdx.x, tid = threadIdx.x;
    const float4* row = (const float4*)(in + (size_t)m * rowlen);
    float4 v[VE / 4];
    float ss = 0.0f, mx = 0.0f;
#pragma unroll
    for (int j = 0; j < VE / 4; j++) {
        v[j] = row[tid + j * 256];
        ss += v[j].x * v[j].x + v[j].y * v[j].y + v[j].z * v[j].z + v[j].w * v[j].w;
        mx = fmaxf(mx, fmaxf(fmaxf(fabsf(v[j].x), fabsf(v[j].y)),
                             fmaxf(fabsf(v[j].z), fabsf(v[j].w))));
    }
    __shared__ float sss[256], smx[256];
    sss[tid] = ss; smx[tid] = mx; __syncthreads();
    for (int s = 128; s > 0; s >>= 1) {
        if (tid < s) {
            sss[tid] += sss[tid + s];
            smx[tid] = fmaxf(smx[tid], smx[tid + s]);
        }
        __syncthreads();
    }
    float r = rsqrtf(sss[0] / (float)rowlen + 1e-6f);
    float cmax = fmaxf(smx[0] * r, 1e-5f);
    float scale = 127.0f / cmax;
    if (tid == 0) inv[m] = cmax / 127.0f;

    ushort4* qrow = (ushort4*)(q + (size_t)m * rowlen);
#pragma unroll
    for (int j = 0; j < VE / 4; j++) {
        int qx = __float2int_rn(v[j].x * r * scale);
        int qy = __float2int_rn(v[j].y * r * scale);
        int qz = __float2int_rn(v[j].z * r * scale);
        int qw = __float2int_rn(v[j].w * r * scale);
        qx = min(max(qx, -128), 127); qy = min(max(qy, -128), 127);
        qz = min(max(qz, -128), 127); qw = min(max(qw, -128), 127);
        ushort4 o;
        o.x = __bfloat16_as_ushort(__float2bfloat16_rn((float)qx));
        o.y = __bfloat16_as_ushort(__float2bfloat16_rn((float)qy));
        o.z = __bfloat16_as_ushort(__float2bfloat16_rn((float)qz));
        o.w = __bfloat16_as_ushort(__float2bfloat16_rn((float)qw));
        qrow[tid + j * 256] = o;
    }
}

// ---------------- bf16 mma.sync GEMM: ldmatrix + 4-stage cp.async, 1 sync/iter ----------------
#define BM 128
#define BN 128
#define SROW 144
#define TILEB (128 * SROW)
#define NSTG 4

__device__ __forceinline__ uint32_t smem_u32(const void* p) {
    uint32_t a;
    asm("{ .reg .u64 t; cvta.to.shared.u64 t, %1; cvt.u32.u64 %0, t; }" : "=r"(a) : "l"(p));
    return a;
}
__device__ __forceinline__ void cp16(uint32_t sdst, const void* gsrc) {
    asm volatile("cp.async.cg.shared.global [%0], [%1], 16;\n" :: "r"(sdst), "l"(gsrc) : "memory");
}
__device__ __forceinline__ void cp_commit() { asm volatile("cp.async.commit_group;\n" ::: "memory"); }
__device__ __forceinline__ void cp_wait0()  { asm volatile("cp.async.wait_group 0;\n" ::: "memory"); }
__device__ __forceinline__ void cp_wait1()  { asm volatile("cp.async.wait_group 1;\n" ::: "memory"); }
__device__ __forceinline__ void cp_wait2()  { asm volatile("cp.async.wait_group 2;\n" ::: "memory"); }
__device__ __forceinline__ void ldsm4(uint32_t* r, uint32_t addr) {
    asm volatile("ldmatrix.sync.aligned.m8n8.x4.shared.b16 {%0,%1,%2,%3}, [%4];"
        : "=r"(r[0]), "=r"(r[1]), "=r"(r[2]), "=r"(r[3]) : "r"(addr));
}
__device__ __forceinline__ void mma_bf16(float* c, const uint32_t* a, const uint32_t* b) {
    asm volatile(
        "mma.sync.aligned.m16n8k16.row.col.f32.bf16.bf16.f32 "
        "{%0,%1,%2,%3},{%4,%5,%6,%7},{%8,%9},{%0,%1,%2,%3};\n"
        : "+f"(c[0]), "+f"(c[1]), "+f"(c[2]), "+f"(c[3])
        : "r"(a[0]), "r"(a[1]), "r"(a[2]), "r"(a[3]), "r"(b[0]), "r"(b[1]));
}

// fast sigmoid-product: silu(a)*b = a*b/(1+e^-a), MUFU-only
__device__ __forceinline__ float swiglu_f(float a, float b) {
    return __fdividef(a * b, 1.0f + __expf(-a));
}

template <bool DUAL>
__global__ void __launch_bounds__(256, 1) gemm_bf(
    const __nv_bfloat16* __restrict__ A,
    const __nv_bfloat16* __restrict__ B1,
    const __nv_bfloat16* __restrict__ B2,
    int K, const float* __restrict__ invA, int wi1, int wi2,
    float* __restrict__ out, int ldo)
{
    extern __shared__ char smem[];
    const int TB = (DUAL ? 3 : 2) * TILEB;
    const uint32_t sb = smem_u32(smem);
    int tid = threadIdx.x;
    int m0 = blockIdx.y * BM, n0 = blockIdx.x * BN;
    size_t Kb = (size_t)K * 2;
    const char* Ab  = (const char*)A  + (size_t)m0 * Kb;
    const char* B1b = (const char*)B1 + (size_t)n0 * Kb;
    const char* B2b = DUAL ? ((const char*)B2 + (size_t)n0 * Kb) : nullptr;
    int KT = K / 64;

    auto issue = [&](int kt) {
        uint32_t base = sb + (kt % NSTG) * TB;
        size_t k0b = (size_t)kt * 128;
#pragma unroll
        for (int it = 0; it < 4; it++) {
            int c = it * 256 + tid;
            int row = c >> 3;
            int col = (c & 7) * 16;
            uint32_t soff = (uint32_t)(row * SROW + col);
            cp16(base + soff,             Ab  + (size_t)row * Kb + k0b + col);
            cp16(base + TILEB + soff,     B1b + (size_t)row * Kb + k0b + col);
            if (DUAL)
                cp16(base + 2 * TILEB + soff, B2b + (size_t)row * Kb + k0b + col);
        }
        cp_commit();
    };

    int wid = tid >> 5, lane = tid & 31;
    int wm = wid >> 2, wn = wid & 3;     // 2 (M) x 4 (N) warps; warp tile 64x32
    int g = lane >> 2, t4 = lane & 3;

    uint32_t offA[4];
#pragma unroll
    for (int im = 0; im < 4; im++)
        offA[im] = (uint32_t)((wm * 64 + im * 16 + (lane & 15)) * SROW + (lane >> 4) * 16);
    uint32_t offB[2];
#pragma unroll
    for (int ib = 0; ib < 2; ib++)
        offB[ib] = (uint32_t)((wn * 32 + ib * 16 + (lane & 7) + ((lane >> 4) & 1) * 8) * SROW
                              + ((lane >> 3) & 1) * 16);

    float c1[4][4][4] = {};
    float c2[4][4][4] = {};

    issue(0);
    issue(1);
    issue(2);
    for (int kt = 0; kt < KT; kt++) {
        if (kt < KT - 2)      cp_wait2();   // allow 2 groups in flight
        else if (kt == KT - 2) cp_wait1();
        else                   cp_wait0();
        __syncthreads();                     // single barrier per k-tile
        if (kt + 3 < KT) issue(kt + 3);      // writes stage (kt-1)%4 — consumed a barrier ago

        const uint32_t base = sb + (kt % NSTG) * TB;
        const uint32_t AsmB = base, B1sm = base + TILEB, B2sm = base + 2 * TILEB;

#pragma unroll
        for (int ks = 0; ks < 4; ks++) {
            const uint32_t kb = ks * 32;
            uint32_t a[4][4];
#pragma unroll
            for (int im = 0; im < 4; im++) ldsm4(a[im], AsmB + offA[im] + kb);

            uint32_t b1[2][4];
#pragma unroll
            for (int ib = 0; ib < 2; ib++) ldsm4(b1[ib], B1sm + offB[ib] + kb);
#pragma unroll
            for (int ib = 0; ib < 2; ib++)
#pragma unroll
                for (int sub = 0; sub < 2; sub++)
#pragma unroll
                    for (int im = 0; im < 4; im++)
                        mma_bf16(c1[im][ib * 2 + sub], a[im], &b1[ib][sub * 2]);

            if constexpr (DUAL) {
                uint32_t b2[2][4];
#pragma unroll
                for (int ib = 0; ib < 2; ib++) ldsm4(b2[ib], B2sm + offB[ib] + kb);
#pragma unroll
                for (int ib = 0; ib < 2; ib++)
#pragma unroll
                    for (int sub = 0; sub < 2; sub++)
#pragma unroll
                        for (int im = 0; im < 4; im++)
                            mma_bf16(c2[im][ib * 2 + sub], a[im], &b2[ib][sub * 2]);
            }
        }
    }

    // epilogue: dequant (+ fast SwiGLU for DUAL). Accumulators are exact integers.
    float dq1 = g_wdq[wi1];
    float dq2 = DUAL ? g_wdq[wi2] : 0.0f;
#pragma unroll
    for (int im = 0; im < 4; im++) {
#pragma unroll
        for (int h2 = 0; h2 < 2; h2++) {
            int row = m0 + wm * 64 + im * 16 + g + h2 * 8;
            float ia = invA[row];
            float s1 = ia * dq1, s2 = ia * dq2;
#pragma unroll
            for (int in = 0; in < 4; in++) {
                int col = n0 + wn * 32 + in * 8 + t4 * 2;
                size_t o = (size_t)row * ldo + col;
                if constexpr (DUAL) {
                    float f1a = c1[im][in][h2 * 2 + 0] * s1;
                    float f1b = c1[im][in][h2 * 2 + 1] * s1;
                    float f2a = c2[im][in][h2 * 2 + 0] * s2;
                    float f2b = c2[im][in][h2 * 2 + 1] * s2;
                    out[o]     = swiglu_f(f1a, f2a);
                    out[o + 1] = swiglu_f(f1b, f2b);
                } else {
                    out[o]     = c1[im][in][h2 * 2 + 0] * s1;
                    out[o + 1] = c1[im][in][h2 * 2 + 1] * s1;
                }
            }
        }
    }
}

// ---------------- launch ----------------
extern "C" void kernel_launch(void* const* d_in, const int* in_sizes, int n_in,
                              void* d_out, int out_size) {
    const float* x  = (const float*)d_in[0];
    const float* w1 = (const float*)d_in[1];
    const float* w2 = (const float*)d_in[2];
    const float* w3 = (const float*)d_in[3];
    float* out = (float*)d_out;

    void *p_w1b, *p_w2b, *p_w3b, *p_xb, *p_hb, *p_h, *p_isx, *p_ish;
    cudaGetSymbolAddress(&p_w1b, g_w1b);
    cudaGetSymbolAddress(&p_w2b, g_w2b);
    cudaGetSymbolAddress(&p_w3b, g_w3b);
    cudaGetSymbolAddress(&p_xb,  g_xb);
    cudaGetSymbolAddress(&p_hb,  g_hb);
    cudaGetSymbolAddress(&p_h,   g_h);
    cudaGetSymbolAddress(&p_isx, g_inv_sx);
    cudaGetSymbolAddress(&p_ish, g_inv_sh);

    const int SM1 = NSTG * 3 * TILEB;   // 4 * 54KB = 216 KB (dual)
    const int SM2 = NSTG * 2 * TILEB;   // 4 * 36KB = 144 KB (single)
    cudaFuncSetAttribute(gemm_bf<true>,  cudaFuncAttributeMaxDynamicSharedMemorySize, SM1);
    cudaFuncSetAttribute(gemm_bf<false>, cudaFuncAttributeMaxDynamicSharedMemorySize, SM2);

    // 1) weight scales (fused partial pass + final)
    wabs_partial3<<<dim3(256, 3), 256>>>(w1, w2, w3);
    wscale_final<<<1, 256>>>();

    // 2) ternary weight quantization, one launch for all three
    quant_w3<<<dim3(NW / 1024, 3), 256>>>(w1, w2, w3,
        (__nv_bfloat16*)p_w1b, (__nv_bfloat16*)p_w2b, (__nv_bfloat16*)p_w3b);

    // 3) rmsnorm + int8-grid quant of x
    act_quant<8><<<M_TOK, 256>>>(x, (__nv_bfloat16*)p_xb, (float*)p_isx, E_DIM);

    // 4) fused dual GEMM1 (w1,w2) + SwiGLU -> h (fp32)
    gemm_bf<true><<<dim3(F_DIM / BN, M_TOK / BM), 256, SM1>>>(
        (const __nv_bfloat16*)p_xb, (const __nv_bfloat16*)p_w1b, (const __nv_bfloat16*)p_w2b,
        E_DIM, (const float*)p_isx, 0, 1, (float*)p_h, F_DIM);

    // 5) rmsnorm + int8-grid quant of h
    act_quant<32><<<M_TOK, 256>>>((const float*)p_h, (__nv_bfloat16*)p_hb, (float*)p_ish, F_DIM);

    // 6) GEMM2 (w3) -> out
    gemm_bf<false><<<dim3(E_DIM / BN, M_TOK / BM), 256, SM2>>>(
        (const __nv_bfloat16*)p_hb, (const __nv_bfloat16*)p_w3b, nullptr,
        F_DIM, (const float*)p_ish, 2, 2, out, E_DIM);
}

// round 15
// speedup vs baseline: 2.5990x; 1.0172x over previous
#include <cuda_runtime.h>
#include <cuda_bf16.h>
#include <cstdint>
#include <math.h>

#define M_TOK 8192
#define E_DIM 2048
#define F_DIM 8192
#define NW    16777216

// ---------------- device scratch ----------------
__device__ __nv_bfloat16 g_w1b[(size_t)F_DIM * E_DIM];
__device__ __nv_bfloat16 g_w2b[(size_t)F_DIM * E_DIM];
__device__ __nv_bfloat16 g_w3b[(size_t)E_DIM * F_DIM];
__device__ __nv_bfloat16 g_xb [(size_t)M_TOK * E_DIM];
__device__ __nv_bfloat16 g_hb [(size_t)M_TOK * F_DIM];
__device__ float  g_h  [(size_t)M_TOK * F_DIM];
__device__ float  g_inv_sx[M_TOK];
__device__ float  g_inv_sh[M_TOK];
__device__ double g_wpart[3 * 256];
__device__ float  g_wdq[3];
__device__ float  g_wsc[3];

// ---------------- weight absmean: one fused launch (blockIdx.y = slot) ----------------
__global__ void wabs_partial3(const float* __restrict__ w0, const float* __restrict__ w1,
                              const float* __restrict__ w2) {
    const float* w = (blockIdx.y == 0) ? w0 : (blockIdx.y == 1) ? w1 : w2;
    __shared__ double sd[256];
    int tid = threadIdx.x;
    double acc = 0.0;
    for (int i = blockIdx.x * 256 + tid; i < NW; i += 256 * gridDim.x)
        acc += (double)fabsf(w[i]);
    sd[tid] = acc; __syncthreads();
    for (int s = 128; s > 0; s >>= 1) {
        if (tid < s) sd[tid] += sd[tid + s];
        __syncthreads();
    }
    if (tid == 0) g_wpart[blockIdx.y * 256 + blockIdx.x] = sd[0];
}

__global__ void wscale_final() {
    __shared__ double sd[256];
    int tid = threadIdx.x;
    for (int wsel = 0; wsel < 3; wsel++) {
        sd[tid] = g_wpart[wsel * 256 + tid]; __syncthreads();
        for (int s = 128; s > 0; s >>= 1) {
            if (tid < s) sd[tid] += sd[tid + s];
            __syncthreads();
        }
        if (tid == 0) {
            float mean = (float)(sd[0] / (double)NW);
            float dq = fmaxf(mean, 1e-5f);
            g_wdq[wsel] = dq;
            g_wsc[wsel] = 1.0f / dq;
        }
        __syncthreads();
    }
}

// ternary weight quant -> bf16 {-1,0,1}; one launch for all 3 weights (blockIdx.y)
__global__ void quant_w3(const float* __restrict__ w0, const float* __restrict__ w1,
                         const float* __restrict__ w2,
                         __nv_bfloat16* __restrict__ q0, __nv_bfloat16* __restrict__ q1,
                         __nv_bfloat16* __restrict__ q2) {
    int wi = blockIdx.y;
    const float* w = (wi == 0) ? w0 : (wi == 1) ? w1 : w2;
    __nv_bfloat16* q = (wi == 0) ? q0 : (wi == 1) ? q1 : q2;
    float s = g_wsc[wi];
    int i = (blockIdx.x * blockDim.x + threadIdx.x) * 4;
    if (i < NW) {
        float4 v = *(const float4*)(w + i);
        ushort4 o;
        o.x = __bfloat16_as_ushort(__float2bfloat16_rn(fminf(fmaxf(rintf(v.x * s), -1.0f), 1.0f)));
        o.y = __bfloat16_as_ushort(__float2bfloat16_rn(fminf(fmaxf(rintf(v.y * s), -1.0f), 1.0f)));
        o.z = __bfloat16_as_ushort(__float2bfloat16_rn(fminf(fmaxf(rintf(v.z * s), -1.0f), 1.0f)));
        o.w = __bfloat16_as_ushort(__float2bfloat16_rn(fminf(fmaxf(rintf(v.w * s), -1.0f), 1.0f)));
        *(ushort4*)(q + i) = o;
    }
}

// rmsnorm + absmax int8-grid quant (stored as exact integers in bf16)
template <int VE>
__global__ void act_quant(const float* __restrict__ in, __nv_bfloat16* __restrict__ q,
                          float* __restrict__ inv, int rowlen) {
    int m = blockIdx.x, tid = threadIdx.x;
    const float4* row = (const float4*)(in + (size_t)m * rowlen);
    float4 v[VE / 4];
    float ss = 0.0f, mx = 0.0f;
#pragma unroll
    for (int j = 0; j < VE / 4; j++) {
        v[j] = row[tid + j * 256];
        ss += v[j].x * v[j].x + v[j].y * v[j].y + v[j].z * v[j].z + v[j].w * v[j].w;
        mx = fmaxf(mx, fmaxf(fmaxf(fabsf(v[j].x), fabsf(v[j].y)),
                             fmaxf(fabsf(v[j].z), fabsf(v[j].w))));
    }
    __shared__ float sss[256], smx[256];
    sss[tid] = ss; smx[tid] = mx; __syncthreads();
    for (int s = 128; s > 0; s >>= 1) {
        if (tid < s) {
            sss[tid] += sss[tid + s];
            smx[tid] = fmaxf(smx[tid], smx[tid + s]);
        }
        __syncthreads();
    }
    float r = rsqrtf(sss[0] / (float)rowlen + 1e-6f);
    float cmax = fmaxf(smx[0] * r, 1e-5f);
    float scale = 127.0f / cmax;
    if (tid == 0) inv[m] = cmax / 127.0f;

    ushort4* qrow = (ushort4*)(q + (size_t)m * rowlen);
#pragma unroll
    for (int j = 0; j < VE / 4; j++) {
        int qx = __float2int_rn(v[j].x * r * scale);
        int qy = __float2int_rn(v[j].y * r * scale);
        int qz = __float2int_rn(v[j].z * r * scale);
        int qw = __float2int_rn(v[j].w * r * scale);
        qx = min(max(qx, -128), 127); qy = min(max(qy, -128), 127);
        qz = min(max(qz, -128), 127); qw = min(max(qw, -128), 127);
        ushort4 o;
        o.x = __bfloat16_as_ushort(__float2bfloat16_rn((float)qx));
        o.y = __bfloat16_as_ushort(__float2bfloat16_rn((float)qy));
        o.z = __bfloat16_as_ushort(__float2bfloat16_rn((float)qz));
        o.w = __bfloat16_as_ushort(__float2bfloat16_rn((float)qw));
        qrow[tid + j * 256] = o;
    }
}

// ---------------- bf16 mma.sync GEMM: ldmatrix + NSTG-stage cp.async, 1 sync/iter ----------------
#define BM 128
#define BN 128
#define SROW 144
#define TILEB (128 * SROW)

__device__ __forceinline__ uint32_t smem_u32(const void* p) {
    uint32_t a;
    asm("{ .reg .u64 t; cvta.to.shared.u64 t, %1; cvt.u32.u64 %0, t; }" : "=r"(a) : "l"(p));
    return a;
}
__device__ __forceinline__ void cp16(uint32_t sdst, const void* gsrc) {
    asm volatile("cp.async.cg.shared.global [%0], [%1], 16;\n" :: "r"(sdst), "l"(gsrc) : "memory");
}
__device__ __forceinline__ void cp_commit() { asm volatile("cp.async.commit_group;\n" ::: "memory"); }
template <int N>
__device__ __forceinline__ void cp_wait() {
    asm volatile("cp.async.wait_group %0;\n" :: "n"(N) : "memory");
}
__device__ __forceinline__ void ldsm4(uint32_t* r, uint32_t addr) {
    asm volatile("ldmatrix.sync.aligned.m8n8.x4.shared.b16 {%0,%1,%2,%3}, [%4];"
        : "=r"(r[0]), "=r"(r[1]), "=r"(r[2]), "=r"(r[3]) : "r"(addr));
}
__device__ __forceinline__ void mma_bf16(float* c, const uint32_t* a, const uint32_t* b) {
    asm volatile(
        "mma.sync.aligned.m16n8k16.row.col.f32.bf16.bf16.f32 "
        "{%0,%1,%2,%3},{%4,%5,%6,%7},{%8,%9},{%0,%1,%2,%3};\n"
        : "+f"(c[0]), "+f"(c[1]), "+f"(c[2]), "+f"(c[3])
        : "r"(a[0]), "r"(a[1]), "r"(a[2]), "r"(a[3]), "r"(b[0]), "r"(b[1]));
}

// fast sigmoid-product: silu(a)*b = a*b/(1+e^-a), MUFU-only
__device__ __forceinline__ float swiglu_f(float a, float b) {
    return __fdividef(a * b, 1.0f + __expf(-a));
}

template <bool DUAL, int NSTG>
__global__ void __launch_bounds__(256, 1) gemm_bf(
    const __nv_bfloat16* __restrict__ A,
    const __nv_bfloat16* __restrict__ B1,
    const __nv_bfloat16* __restrict__ B2,
    int K, const float* __restrict__ invA, int wi1, int wi2,
    float* __restrict__ out, int ldo)
{
    extern __shared__ char smem[];
    const int TB = (DUAL ? 3 : 2) * TILEB;
    const uint32_t sb = smem_u32(smem);
    int tid = threadIdx.x;
    int m0 = blockIdx.y * BM, n0 = blockIdx.x * BN;
    size_t Kb = (size_t)K * 2;
    const char* Ab  = (const char*)A  + (size_t)m0 * Kb;
    const char* B1b = (const char*)B1 + (size_t)n0 * Kb;
    const char* B2b = DUAL ? ((const char*)B2 + (size_t)n0 * Kb) : nullptr;
    int KT = K / 64;

    auto issue = [&](int kt) {
        uint32_t base = sb + (kt % NSTG) * TB;
        size_t k0b = (size_t)kt * 128;
#pragma unroll
        for (int it = 0; it < 4; it++) {
            int c = it * 256 + tid;
            int row = c >> 3;
            int col = (c & 7) * 16;
            uint32_t soff = (uint32_t)(row * SROW + col);
            cp16(base + soff,             Ab  + (size_t)row * Kb + k0b + col);
            cp16(base + TILEB + soff,     B1b + (size_t)row * Kb + k0b + col);
            if (DUAL)
                cp16(base + 2 * TILEB + soff, B2b + (size_t)row * Kb + k0b + col);
        }
        cp_commit();
    };

    int wid = tid >> 5, lane = tid & 31;
    int wm = wid >> 2, wn = wid & 3;     // 2 (M) x 4 (N) warps; warp tile 64x32
    int g = lane >> 2, t4 = lane & 3;

    uint32_t offA[4];
#pragma unroll
    for (int im = 0; im < 4; im++)
        offA[im] = (uint32_t)((wm * 64 + im * 16 + (lane & 15)) * SROW + (lane >> 4) * 16);
    uint32_t offB[2];
#pragma unroll
    for (int ib = 0; ib < 2; ib++)
        offB[ib] = (uint32_t)((wn * 32 + ib * 16 + (lane & 7) + ((lane >> 4) & 1) * 8) * SROW
                              + ((lane >> 3) & 1) * 16);

    float c1[4][4][4] = {};
    float c2[4][4][4] = {};

    // prologue: fill NSTG-1 stages
#pragma unroll
    for (int p = 0; p < NSTG - 1; p++)
        if (p < KT) issue(p);

    for (int kt = 0; kt < KT; kt++) {
        int rem = KT - 1 - kt;                 // groups still outstanding after this wait
        if (rem >= NSTG - 2)      cp_wait<NSTG - 2>();
        else if (rem == 3)        cp_wait<3>();
        else if (rem == 2)        cp_wait<2>();
        else if (rem == 1)        cp_wait<1>();
        else                      cp_wait<0>();
        __syncthreads();
        if (kt + NSTG - 1 < KT) issue(kt + NSTG - 1);

        const uint32_t base = sb + (kt % NSTG) * TB;
        const uint32_t AsmB = base, B1sm = base + TILEB, B2sm = base + 2 * TILEB;

#pragma unroll
        for (int ks = 0; ks < 4; ks++) {
            const uint32_t kb = ks * 32;
            uint32_t a[4][4];
#pragma unroll
            for (int im = 0; im < 4; im++) ldsm4(a[im], AsmB + offA[im] + kb);

            uint32_t b1[2][4];
#pragma unroll
            for (int ib = 0; ib < 2; ib++) ldsm4(b1[ib], B1sm + offB[ib] + kb);
#pragma unroll
            for (int ib = 0; ib < 2; ib++)
#pragma unroll
                for (int sub = 0; sub < 2; sub++)
#pragma unroll
                    for (int im = 0; im < 4; im++)
                        mma_bf16(c1[im][ib * 2 + sub], a[im], &b1[ib][sub * 2]);

            if constexpr (DUAL) {
                uint32_t b2[2][4];
#pragma unroll
                for (int ib = 0; ib < 2; ib++) ldsm4(b2[ib], B2sm + offB[ib] + kb);
#pragma unroll
                for (int ib = 0; ib < 2; ib++)
#pragma unroll
                    for (int sub = 0; sub < 2; sub++)
#pragma unroll
                        for (int im = 0; im < 4; im++)
                            mma_bf16(c2[im][ib * 2 + sub], a[im], &b2[ib][sub * 2]);
            }
        }
    }

    // epilogue: dequant (+ fast SwiGLU for DUAL). Accumulators are exact integers.
    float dq1 = g_wdq[wi1];
    float dq2 = DUAL ? g_wdq[wi2] : 0.0f;
#pragma unroll
    for (int im = 0; im < 4; im++) {
#pragma unroll
        for (int h2 = 0; h2 < 2; h2++) {
            int row = m0 + wm * 64 + im * 16 + g + h2 * 8;
            float ia = invA[row];
            float s1 = ia * dq1, s2 = ia * dq2;
#pragma unroll
            for (int in = 0; in < 4; in++) {
                int col = n0 + wn * 32 + in * 8 + t4 * 2;
                size_t o = (size_t)row * ldo + col;
                if constexpr (DUAL) {
                    float f1a = c1[im][in][h2 * 2 + 0] * s1;
                    float f1b = c1[im][in][h2 * 2 + 1] * s1;
                    float f2a = c2[im][in][h2 * 2 + 0] * s2;
                    float f2b = c2[im][in][h2 * 2 + 1] * s2;
                    float2 hv = make_float2(swiglu_f(f1a, f2a), swiglu_f(f1b, f2b));
                    *(float2*)(out + o) = hv;
                } else {
                    float2 hv = make_float2(c1[im][in][h2 * 2 + 0] * s1,
                                            c1[im][in][h2 * 2 + 1] * s1);
                    *(float2*)(out + o) = hv;
                }
            }
        }
    }
}

// ---------------- launch ----------------
extern "C" void kernel_launch(void* const* d_in, const int* in_sizes, int n_in,
                              void* d_out, int out_size) {
    const float* x  = (const float*)d_in[0];
    const float* w1 = (const float*)d_in[1];
    const float* w2 = (const float*)d_in[2];
    const float* w3 = (const float*)d_in[3];
    float* out = (float*)d_out;

    void *p_w1b, *p_w2b, *p_w3b, *p_xb, *p_hb, *p_h, *p_isx, *p_ish;
    cudaGetSymbolAddress(&p_w1b, g_w1b);
    cudaGetSymbolAddress(&p_w2b, g_w2b);
    cudaGetSymbolAddress(&p_w3b, g_w3b);
    cudaGetSymbolAddress(&p_xb,  g_xb);
    cudaGetSymbolAddress(&p_hb,  g_hb);
    cudaGetSymbolAddress(&p_h,   g_h);
    cudaGetSymbolAddress(&p_isx, g_inv_sx);
    cudaGetSymbolAddress(&p_ish, g_inv_sh);

    const int SM1 = 4 * 3 * TILEB;   // GEMM1: 4 stages * 54 KB = 216 KB
    const int SM2 = 6 * 2 * TILEB;   // GEMM2: 6 stages * 36 KB = 216 KB
    cudaFuncSetAttribute((const void*)gemm_bf<true, 4>,
                         cudaFuncAttributeMaxDynamicSharedMemorySize, SM1);
    cudaFuncSetAttribute((const void*)gemm_bf<false, 6>,
                         cudaFuncAttributeMaxDynamicSharedMemorySize, SM2);

    // 1) weight scales (fused partial pass + final)
    wabs_partial3<<<dim3(256, 3), 256>>>(w1, w2, w3);
    wscale_final<<<1, 256>>>();

    // 2) ternary weight quantization, one launch for all three
    quant_w3<<<dim3(NW / 1024, 3), 256>>>(w1, w2, w3,
        (__nv_bfloat16*)p_w1b, (__nv_bfloat16*)p_w2b, (__nv_bfloat16*)p_w3b);

    // 3) rmsnorm + int8-grid quant of x
    act_quant<8><<<M_TOK, 256>>>(x, (__nv_bfloat16*)p_xb, (float*)p_isx, E_DIM);

    // 4) fused dual GEMM1 (w1,w2) + SwiGLU -> h (fp32)
    gemm_bf<true, 4><<<dim3(F_DIM / BN, M_TOK / BM), 256, SM1>>>(
        (const __nv_bfloat16*)p_xb, (const __nv_bfloat16*)p_w1b, (const __nv_bfloat16*)p_w2b,
        E_DIM, (const float*)p_isx, 0, 1, (float*)p_h, F_DIM);

    // 5) rmsnorm + int8-grid quant of h
    act_quant<32><<<M_TOK, 256>>>((const float*)p_h, (__nv_bfloat16*)p_hb, (float*)p_ish, F_DIM);

    // 6) GEMM2 (w3, deep 6-stage pipeline) -> out
    gemm_bf<false, 6><<<dim3(E_DIM / BN, M_TOK / BM), 256, SM2>>>(
        (const __nv_bfloat16*)p_hb, (const __nv_bfloat16*)p_w3b, nullptr,
        F_DIM, (const float*)p_ish, 2, 2, out, E_DIM);
}

// round 16
// speedup vs baseline: 2.7600x; 1.0620x over previous
#include <cuda_runtime.h>
#include <cuda_bf16.h>
#include <cstdint>
#include <math.h>

#define M_TOK 8192
#define E_DIM 2048
#define F_DIM 8192
#define NW    16777216

// ---------------- device scratch ----------------
__device__ __nv_bfloat16 g_w1b[(size_t)F_DIM * E_DIM];
__device__ __nv_bfloat16 g_w2b[(size_t)F_DIM * E_DIM];
__device__ __nv_bfloat16 g_w3b[(size_t)E_DIM * F_DIM];
__device__ __nv_bfloat16 g_xb [(size_t)M_TOK * E_DIM];
__device__ __nv_bfloat16 g_hb [(size_t)M_TOK * F_DIM];
__device__ float  g_h  [(size_t)M_TOK * F_DIM];
__device__ float  g_inv_sx[M_TOK];
__device__ float  g_inv_sh[M_TOK];
__device__ double g_wpart[3 * 256];
__device__ float  g_wdq[3];
__device__ float  g_wsc[3];

// ---------------- weight absmean: one fused launch (blockIdx.y = slot) ----------------
__global__ void wabs_partial3(const float* __restrict__ w0, const float* __restrict__ w1,
                              const float* __restrict__ w2) {
    const float* w = (blockIdx.y == 0) ? w0 : (blockIdx.y == 1) ? w1 : w2;
    __shared__ double sd[256];
    int tid = threadIdx.x;
    double acc = 0.0;
    for (int i = blockIdx.x * 256 + tid; i < NW; i += 256 * gridDim.x)
        acc += (double)fabsf(w[i]);
    sd[tid] = acc; __syncthreads();
    for (int s = 128; s > 0; s >>= 1) {
        if (tid < s) sd[tid] += sd[tid + s];
        __syncthreads();
    }
    if (tid == 0) g_wpart[blockIdx.y * 256 + blockIdx.x] = sd[0];
}

__global__ void wscale_final() {
    __shared__ double sd[256];
    int tid = threadIdx.x;
    for (int wsel = 0; wsel < 3; wsel++) {
        sd[tid] = g_wpart[wsel * 256 + tid]; __syncthreads();
        for (int s = 128; s > 0; s >>= 1) {
            if (tid < s) sd[tid] += sd[tid + s];
            __syncthreads();
        }
        if (tid == 0) {
            float mean = (float)(sd[0] / (double)NW);
            float dq = fmaxf(mean, 1e-5f);
            g_wdq[wsel] = dq;
            g_wsc[wsel] = 1.0f / dq;
        }
        __syncthreads();
    }
}

// ternary weight quant -> bf16 {-1,0,1}; one launch for all 3 weights (blockIdx.y)
__global__ void quant_w3(const float* __restrict__ w0, const float* __restrict__ w1,
                         const float* __restrict__ w2,
                         __nv_bfloat16* __restrict__ q0, __nv_bfloat16* __restrict__ q1,
                         __nv_bfloat16* __restrict__ q2) {
    int wi = blockIdx.y;
    const float* w = (wi == 0) ? w0 : (wi == 1) ? w1 : w2;
    __nv_bfloat16* q = (wi == 0) ? q0 : (wi == 1) ? q1 : q2;
    float s = g_wsc[wi];
    int i = (blockIdx.x * blockDim.x + threadIdx.x) * 4;
    if (i < NW) {
        float4 v = *(const float4*)(w + i);
        ushort4 o;
        o.x = __bfloat16_as_ushort(__float2bfloat16_rn(fminf(fmaxf(rintf(v.x * s), -1.0f), 1.0f)));
        o.y = __bfloat16_as_ushort(__float2bfloat16_rn(fminf(fmaxf(rintf(v.y * s), -1.0f), 1.0f)));
        o.z = __bfloat16_as_ushort(__float2bfloat16_rn(fminf(fmaxf(rintf(v.z * s), -1.0f), 1.0f)));
        o.w = __bfloat16_as_ushort(__float2bfloat16_rn(fminf(fmaxf(rintf(v.w * s), -1.0f), 1.0f)));
        *(ushort4*)(q + i) = o;
    }
}

// rmsnorm + absmax int8-grid quant (stored as exact integers in bf16)
template <int VE>
__global__ void act_quant(const float* __restrict__ in, __nv_bfloat16* __restrict__ q,
                          float* __restrict__ inv, int rowlen) {
    int m = blockIdx.x, tid = threadIdx.x;
    const float4* row = (const float4*)(in + (size_t)m * rowlen);
    float4 v[VE / 4];
    float ss = 0.0f, mx = 0.0f;
#pragma unroll
    for (int j = 0; j < VE / 4; j++) {
        v[j] = row[tid + j * 256];
        ss += v[j].x * v[j].x + v[j].y * v[j].y + v[j].z * v[j].z + v[j].w * v[j].w;
        mx = fmaxf(mx, fmaxf(fmaxf(fabsf(v[j].x), fabsf(v[j].y)),
                             fmaxf(fabsf(v[j].z), fabsf(v[j].w))));
    }
    __shared__ float sss[256], smx[256];
    sss[tid] = ss; smx[tid] = mx; __syncthreads();
    for (int s = 128; s > 0; s >>= 1) {
        if (tid < s) {
            sss[tid] += sss[tid + s];
            smx[tid] = fmaxf(smx[tid], smx[tid + s]);
        }
        __syncthreads();
    }
    float r = rsqrtf(sss[0] / (float)rowlen + 1e-6f);
    float cmax = fmaxf(smx[0] * r, 1e-5f);
    float scale = 127.0f / cmax;
    if (tid == 0) inv[m] = cmax / 127.0f;

    ushort4* qrow = (ushort4*)(q + (size_t)m * rowlen);
#pragma unroll
    for (int j = 0; j < VE / 4; j++) {
        int qx = __float2int_rn(v[j].x * r * scale);
        int qy = __float2int_rn(v[j].y * r * scale);
        int qz = __float2int_rn(v[j].z * r * scale);
        int qw = __float2int_rn(v[j].w * r * scale);
        qx = min(max(qx, -128), 127); qy = min(max(qy, -128), 127);
        qz = min(max(qz, -128), 127); qw = min(max(qw, -128), 127);
        ushort4 o;
        o.x = __bfloat16_as_ushort(__float2bfloat16_rn((float)qx));
        o.y = __bfloat16_as_ushort(__float2bfloat16_rn((float)qy));
        o.z = __bfloat16_as_ushort(__float2bfloat16_rn((float)qz));
        o.w = __bfloat16_as_ushort(__float2bfloat16_rn((float)qw));
        qrow[tid + j * 256] = o;
    }
}

// ---------------- bf16 mma.sync GEMM: ldmatrix + NSTG-stage cp.async, 1 sync/iter ----------------
#define BM 128
#define BN 128
#define SROW 144
#define TILEB (128 * SROW)

__device__ __forceinline__ uint32_t smem_u32(const void* p) {
    uint32_t a;
    asm("{ .reg .u64 t; cvta.to.shared.u64 t, %1; cvt.u32.u64 %0, t; }" : "=r"(a) : "l"(p));
    return a;
}
__device__ __forceinline__ void cp16(uint32_t sdst, const void* gsrc) {
    asm volatile("cp.async.cg.shared.global [%0], [%1], 16;\n" :: "r"(sdst), "l"(gsrc) : "memory");
}
__device__ __forceinline__ void cp_commit() { asm volatile("cp.async.commit_group;\n" ::: "memory"); }
template <int N>
__device__ __forceinline__ void cp_wait() {
    asm volatile("cp.async.wait_group %0;\n" :: "n"(N) : "memory");
}
__device__ __forceinline__ void ldsm4(uint32_t* r, uint32_t addr) {
    asm volatile("ldmatrix.sync.aligned.m8n8.x4.shared.b16 {%0,%1,%2,%3}, [%4];"
        : "=r"(r[0]), "=r"(r[1]), "=r"(r[2]), "=r"(r[3]) : "r"(addr));
}
__device__ __forceinline__ void mma_bf16(float* c, const uint32_t* a, const uint32_t* b) {
    asm volatile(
        "mma.sync.aligned.m16n8k16.row.col.f32.bf16.bf16.f32 "
        "{%0,%1,%2,%3},{%4,%5,%6,%7},{%8,%9},{%0,%1,%2,%3};\n"
        : "+f"(c[0]), "+f"(c[1]), "+f"(c[2]), "+f"(c[3])
        : "r"(a[0]), "r"(a[1]), "r"(a[2]), "r"(a[3]), "r"(b[0]), "r"(b[1]));
}

// fast sigmoid-product: silu(a)*b = a*b/(1+e^-a), MUFU-only
__device__ __forceinline__ float swiglu_f(float a, float b) {
    return __fdividef(a * b, 1.0f + __expf(-a));
}

template <bool DUAL, int NSTG, int OCC>
__global__ void __launch_bounds__(256, OCC) gemm_bf(
    const __nv_bfloat16* __restrict__ A,
    const __nv_bfloat16* __restrict__ B1,
    const __nv_bfloat16* __restrict__ B2,
    int K, const float* __restrict__ invA, int wi1, int wi2,
    float* __restrict__ out, int ldo)
{
    extern __shared__ char smem[];
    const int TB = (DUAL ? 3 : 2) * TILEB;
    const uint32_t sb = smem_u32(smem);
    int tid = threadIdx.x;
    int m0 = blockIdx.y * BM, n0 = blockIdx.x * BN;
    size_t Kb = (size_t)K * 2;
    const char* Ab  = (const char*)A  + (size_t)m0 * Kb;
    const char* B1b = (const char*)B1 + (size_t)n0 * Kb;
    const char* B2b = DUAL ? ((const char*)B2 + (size_t)n0 * Kb) : nullptr;
    int KT = K / 64;

    auto issue = [&](int kt) {
        uint32_t base = sb + (kt % NSTG) * TB;
        size_t k0b = (size_t)kt * 128;
#pragma unroll
        for (int it = 0; it < 4; it++) {
            int c = it * 256 + tid;
            int row = c >> 3;
            int col = (c & 7) * 16;
            uint32_t soff = (uint32_t)(row * SROW + col);
            cp16(base + soff,             Ab  + (size_t)row * Kb + k0b + col);
            cp16(base + TILEB + soff,     B1b + (size_t)row * Kb + k0b + col);
            if (DUAL)
                cp16(base + 2 * TILEB + soff, B2b + (size_t)row * Kb + k0b + col);
        }
        cp_commit();
    };

    int wid = tid >> 5, lane = tid & 31;
    int wm = wid >> 2, wn = wid & 3;     // 2 (M) x 4 (N) warps; warp tile 64x32
    int g = lane >> 2, t4 = lane & 3;

    uint32_t offA[4];
#pragma unroll
    for (int im = 0; im < 4; im++)
        offA[im] = (uint32_t)((wm * 64 + im * 16 + (lane & 15)) * SROW + (lane >> 4) * 16);
    uint32_t offB[2];
#pragma unroll
    for (int ib = 0; ib < 2; ib++)
        offB[ib] = (uint32_t)((wn * 32 + ib * 16 + (lane & 7) + ((lane >> 4) & 1) * 8) * SROW
                              + ((lane >> 3) & 1) * 16);

    float c1[4][4][4] = {};
    float c2[4][4][4] = {};

    // prologue: fill NSTG-1 stages
#pragma unroll
    for (int p = 0; p < NSTG - 1; p++)
        if (p < KT) issue(p);

    for (int kt = 0; kt < KT; kt++) {
        int rem = KT - 1 - kt;                 // groups still outstanding after this wait
        if (rem >= NSTG - 2)      cp_wait<NSTG - 2>();
        else if (rem == 3)        cp_wait<3>();
        else if (rem == 2)        cp_wait<2>();
        else if (rem == 1)        cp_wait<1>();
        else                      cp_wait<0>();
        __syncthreads();
        if (kt + NSTG - 1 < KT) issue(kt + NSTG - 1);

        const uint32_t base = sb + (kt % NSTG) * TB;
        const uint32_t AsmB = base, B1sm = base + TILEB, B2sm = base + 2 * TILEB;

#pragma unroll
        for (int ks = 0; ks < 4; ks++) {
            const uint32_t kb = ks * 32;
            uint32_t a[4][4];
#pragma unroll
            for (int im = 0; im < 4; im++) ldsm4(a[im], AsmB + offA[im] + kb);

            uint32_t b1[2][4];
#pragma unroll
            for (int ib = 0; ib < 2; ib++) ldsm4(b1[ib], B1sm + offB[ib] + kb);
#pragma unroll
            for (int ib = 0; ib < 2; ib++)
#pragma unroll
                for (int sub = 0; sub < 2; sub++)
#pragma unroll
                    for (int im = 0; im < 4; im++)
                        mma_bf16(c1[im][ib * 2 + sub], a[im], &b1[ib][sub * 2]);

            if constexpr (DUAL) {
                uint32_t b2[2][4];
#pragma unroll
                for (int ib = 0; ib < 2; ib++) ldsm4(b2[ib], B2sm + offB[ib] + kb);
#pragma unroll
                for (int ib = 0; ib < 2; ib++)
#pragma unroll
                    for (int sub = 0; sub < 2; sub++)
#pragma unroll
                        for (int im = 0; im < 4; im++)
                            mma_bf16(c2[im][ib * 2 + sub], a[im], &b2[ib][sub * 2]);
            }
        }
    }

    // epilogue: dequant (+ fast SwiGLU for DUAL). Accumulators are exact integers.
    float dq1 = g_wdq[wi1];
    float dq2 = DUAL ? g_wdq[wi2] : 0.0f;
#pragma unroll
    for (int im = 0; im < 4; im++) {
#pragma unroll
        for (int h2 = 0; h2 < 2; h2++) {
            int row = m0 + wm * 64 + im * 16 + g + h2 * 8;
            float ia = invA[row];
            float s1 = ia * dq1, s2 = ia * dq2;
#pragma unroll
            for (int in = 0; in < 4; in++) {
                int col = n0 + wn * 32 + in * 8 + t4 * 2;
                size_t o = (size_t)row * ldo + col;
                if constexpr (DUAL) {
                    float f1a = c1[im][in][h2 * 2 + 0] * s1;
                    float f1b = c1[im][in][h2 * 2 + 1] * s1;
                    float f2a = c2[im][in][h2 * 2 + 0] * s2;
                    float f2b = c2[im][in][h2 * 2 + 1] * s2;
                    float2 hv = make_float2(swiglu_f(f1a, f2a), swiglu_f(f1b, f2b));
                    *(float2*)(out + o) = hv;
                } else {
                    float2 hv = make_float2(c1[im][in][h2 * 2 + 0] * s1,
                                            c1[im][in][h2 * 2 + 1] * s1);
                    *(float2*)(out + o) = hv;
                }
            }
        }
    }
}

// ---------------- launch ----------------
extern "C" void kernel_launch(void* const* d_in, const int* in_sizes, int n_in,
                              void* d_out, int out_size) {
    const float* x  = (const float*)d_in[0];
    const float* w1 = (const float*)d_in[1];
    const float* w2 = (const float*)d_in[2];
    const float* w3 = (const float*)d_in[3];
    float* out = (float*)d_out;

    void *p_w1b, *p_w2b, *p_w3b, *p_xb, *p_hb, *p_h, *p_isx, *p_ish;
    cudaGetSymbolAddress(&p_w1b, g_w1b);
    cudaGetSymbolAddress(&p_w2b, g_w2b);
    cudaGetSymbolAddress(&p_w3b, g_w3b);
    cudaGetSymbolAddress(&p_xb,  g_xb);
    cudaGetSymbolAddress(&p_hb,  g_hb);
    cudaGetSymbolAddress(&p_h,   g_h);
    cudaGetSymbolAddress(&p_isx, g_inv_sx);
    cudaGetSymbolAddress(&p_ish, g_inv_sh);

    const int SM1 = 4 * 3 * TILEB;   // GEMM1: 4 stages * 54 KB = 216 KB, 1 CTA/SM
    const int SM2 = 3 * 2 * TILEB;   // GEMM2: 3 stages * 36 KB = 108 KB, 2 CTAs/SM
    cudaFuncSetAttribute((const void*)gemm_bf<true, 4, 1>,
                         cudaFuncAttributeMaxDynamicSharedMemorySize, SM1);
    cudaFuncSetAttribute((const void*)gemm_bf<false, 3, 2>,
                         cudaFuncAttributeMaxDynamicSharedMemorySize, SM2);

    // 1) weight scales (fused partial pass + final)
    wabs_partial3<<<dim3(256, 3), 256>>>(w1, w2, w3);
    wscale_final<<<1, 256>>>();

    // 2) ternary weight quantization, one launch for all three
    quant_w3<<<dim3(NW / 1024, 3), 256>>>(w1, w2, w3,
        (__nv_bfloat16*)p_w1b, (__nv_bfloat16*)p_w2b, (__nv_bfloat16*)p_w3b);

    // 3) rmsnorm + int8-grid quant of x
    act_quant<8><<<M_TOK, 256>>>(x, (__nv_bfloat16*)p_xb, (float*)p_isx, E_DIM);

    // 4) fused dual GEMM1 (w1,w2) + SwiGLU -> h (fp32)
    gemm_bf<true, 4, 1><<<dim3(F_DIM / BN, M_TOK / BM), 256, SM1>>>(
        (const __nv_bfloat16*)p_xb, (const __nv_bfloat16*)p_w1b, (const __nv_bfloat16*)p_w2b,
        E_DIM, (const float*)p_isx, 0, 1, (float*)p_h, F_DIM);

    // 5) rmsnorm + int8-grid quant of h
    act_quant<32><<<M_TOK, 256>>>((const float*)p_h, (__nv_bfloat16*)p_hb, (float*)p_ish, F_DIM);

    // 6) GEMM2 (w3, 3-stage, 2 CTAs/SM) -> out
    gemm_bf<false, 3, 2><<<dim3(E_DIM / BN, M_TOK / BM), 256, SM2>>>(
        (const __nv_bfloat16*)p_hb, (const __nv_bfloat16*)p_w3b, nullptr,
        F_DIM, (const float*)p_ish, 2, 2, out, E_DIM);
}

// round 17
// speedup vs baseline: 2.8672x; 1.0389x over previous
#include <cuda_runtime.h>
#include <cuda_bf16.h>
#include <cstdint>
#include <math.h>

#define M_TOK 8192
#define E_DIM 2048
#define F_DIM 8192
#define NW    16777216

// ---------------- device scratch ----------------
__device__ __nv_bfloat16 g_w1b[(size_t)F_DIM * E_DIM];
__device__ __nv_bfloat16 g_w2b[(size_t)F_DIM * E_DIM];
__device__ __nv_bfloat16 g_w3b[(size_t)E_DIM * F_DIM];
__device__ __nv_bfloat16 g_xb [(size_t)M_TOK * E_DIM];
__device__ __nv_bfloat16 g_hb [(size_t)M_TOK * F_DIM];
__device__ float  g_t1 [(size_t)M_TOK * F_DIM];
__device__ float  g_t2 [(size_t)M_TOK * F_DIM];
__device__ float  g_inv_sx[M_TOK];
__device__ float  g_inv_sh[M_TOK];
__device__ double g_wpart[3 * 256];
__device__ float  g_wdq[3];
__device__ float  g_wsc[3];

// ---------------- weight absmean: one fused launch (blockIdx.y = slot) ----------------
__global__ void wabs_partial3(const float* __restrict__ w0, const float* __restrict__ w1,
                              const float* __restrict__ w2) {
    const float* w = (blockIdx.y == 0) ? w0 : (blockIdx.y == 1) ? w1 : w2;
    __shared__ double sd[256];
    int tid = threadIdx.x;
    double acc = 0.0;
    for (int i = blockIdx.x * 256 + tid; i < NW; i += 256 * gridDim.x)
        acc += (double)fabsf(w[i]);
    sd[tid] = acc; __syncthreads();
    for (int s = 128; s > 0; s >>= 1) {
        if (tid < s) sd[tid] += sd[tid + s];
        __syncthreads();
    }
    if (tid == 0) g_wpart[blockIdx.y * 256 + blockIdx.x] = sd[0];
}

__global__ void wscale_final() {
    __shared__ double sd[256];
    int tid = threadIdx.x;
    for (int wsel = 0; wsel < 3; wsel++) {
        sd[tid] = g_wpart[wsel * 256 + tid]; __syncthreads();
        for (int s = 128; s > 0; s >>= 1) {
            if (tid < s) sd[tid] += sd[tid + s];
            __syncthreads();
        }
        if (tid == 0) {
            float mean = (float)(sd[0] / (double)NW);
            float dq = fmaxf(mean, 1e-5f);
            g_wdq[wsel] = dq;
            g_wsc[wsel] = 1.0f / dq;
        }
        __syncthreads();
    }
}

// ternary weight quant -> bf16 {-1,0,1}; one launch for all 3 weights (blockIdx.y)
__global__ void quant_w3(const float* __restrict__ w0, const float* __restrict__ w1,
                         const float* __restrict__ w2,
                         __nv_bfloat16* __restrict__ q0, __nv_bfloat16* __restrict__ q1,
                         __nv_bfloat16* __restrict__ q2) {
    int wi = blockIdx.y;
    const float* w = (wi == 0) ? w0 : (wi == 1) ? w1 : w2;
    __nv_bfloat16* q = (wi == 0) ? q0 : (wi == 1) ? q1 : q2;
    float s = g_wsc[wi];
    int i = (blockIdx.x * blockDim.x + threadIdx.x) * 4;
    if (i < NW) {
        float4 v = *(const float4*)(w + i);
        ushort4 o;
        o.x = __bfloat16_as_ushort(__float2bfloat16_rn(fminf(fmaxf(rintf(v.x * s), -1.0f), 1.0f)));
        o.y = __bfloat16_as_ushort(__float2bfloat16_rn(fminf(fmaxf(rintf(v.y * s), -1.0f), 1.0f)));
        o.z = __bfloat16_as_ushort(__float2bfloat16_rn(fminf(fmaxf(rintf(v.z * s), -1.0f), 1.0f)));
        o.w = __bfloat16_as_ushort(__float2bfloat16_rn(fminf(fmaxf(rintf(v.w * s), -1.0f), 1.0f)));
        *(ushort4*)(q + i) = o;
    }
}

// rmsnorm + absmax int8-grid quant of fp32 x (stored as exact integers in bf16)
__global__ void act_quant_x(const float* __restrict__ in, __nv_bfloat16* __restrict__ q,
                            float* __restrict__ inv) {
    const int rowlen = E_DIM;
    int m = blockIdx.x, tid = threadIdx.x;
    const float4* row = (const float4*)(in + (size_t)m * rowlen);
    float4 v[2];
    float ss = 0.0f, mx = 0.0f;
#pragma unroll
    for (int j = 0; j < 2; j++) {
        v[j] = row[tid + j * 256];
        ss += v[j].x * v[j].x + v[j].y * v[j].y + v[j].z * v[j].z + v[j].w * v[j].w;
        mx = fmaxf(mx, fmaxf(fmaxf(fabsf(v[j].x), fabsf(v[j].y)),
                             fmaxf(fabsf(v[j].z), fabsf(v[j].w))));
    }
    __shared__ float sss[256], smx[256];
    sss[tid] = ss; smx[tid] = mx; __syncthreads();
    for (int s = 128; s > 0; s >>= 1) {
        if (tid < s) {
            sss[tid] += sss[tid + s];
            smx[tid] = fmaxf(smx[tid], smx[tid + s]);
        }
        __syncthreads();
    }
    float r = rsqrtf(sss[0] / (float)rowlen + 1e-6f);
    float cmax = fmaxf(smx[0] * r, 1e-5f);
    float scale = 127.0f / cmax;
    if (tid == 0) inv[m] = cmax / 127.0f;

    ushort4* qrow = (ushort4*)(q + (size_t)m * rowlen);
#pragma unroll
    for (int j = 0; j < 2; j++) {
        int qx = __float2int_rn(v[j].x * r * scale);
        int qy = __float2int_rn(v[j].y * r * scale);
        int qz = __float2int_rn(v[j].z * r * scale);
        int qw = __float2int_rn(v[j].w * r * scale);
        qx = min(max(qx, -128), 127); qy = min(max(qy, -128), 127);
        qz = min(max(qz, -128), 127); qw = min(max(qw, -128), 127);
        ushort4 o;
        o.x = __bfloat16_as_ushort(__float2bfloat16_rn((float)qx));
        o.y = __bfloat16_as_ushort(__float2bfloat16_rn((float)qy));
        o.z = __bfloat16_as_ushort(__float2bfloat16_rn((float)qz));
        o.w = __bfloat16_as_ushort(__float2bfloat16_rn((float)qw));
        qrow[tid + j * 256] = o;
    }
}

// fast sigmoid-product: silu(a)*b = a*b/(1+e^-a), MUFU-only
__device__ __forceinline__ float swiglu_f(float a, float b) {
    return __fdividef(a * b, 1.0f + __expf(-a));
}

// SwiGLU(t1,t2) -> rmsnorm -> absmax int8-grid quant (bf16 ints). R8-proven pattern.
__global__ void act_quant_swiglu(const float* __restrict__ t1, const float* __restrict__ t2,
                                 __nv_bfloat16* __restrict__ q, float* __restrict__ inv) {
    const int rowlen = F_DIM;
    int m = blockIdx.x, tid = threadIdx.x;
    const float4* r1 = (const float4*)(t1 + (size_t)m * rowlen);
    const float4* r2 = (const float4*)(t2 + (size_t)m * rowlen);
    float4 v[8];
    float ss = 0.0f, mx = 0.0f;
#pragma unroll
    for (int j = 0; j < 8; j++) {
        float4 a = r1[tid + j * 256];
        float4 b = r2[tid + j * 256];
        float4 h;
        h.x = swiglu_f(a.x, b.x);
        h.y = swiglu_f(a.y, b.y);
        h.z = swiglu_f(a.z, b.z);
        h.w = swiglu_f(a.w, b.w);
        v[j] = h;
        ss += h.x * h.x + h.y * h.y + h.z * h.z + h.w * h.w;
        mx = fmaxf(mx, fmaxf(fmaxf(fabsf(h.x), fabsf(h.y)),
                             fmaxf(fabsf(h.z), fabsf(h.w))));
    }
    __shared__ float sss[256], smx[256];
    sss[tid] = ss; smx[tid] = mx; __syncthreads();
    for (int s = 128; s > 0; s >>= 1) {
        if (tid < s) {
            sss[tid] += sss[tid + s];
            smx[tid] = fmaxf(smx[tid], smx[tid + s]);
        }
        __syncthreads();
    }
    float r = rsqrtf(sss[0] / (float)rowlen + 1e-6f);
    float cmax = fmaxf(smx[0] * r, 1e-5f);
    float scale = 127.0f / cmax;
    if (tid == 0) inv[m] = cmax / 127.0f;

    ushort4* qrow = (ushort4*)(q + (size_t)m * rowlen);
#pragma unroll
    for (int j = 0; j < 8; j++) {
        int qx = __float2int_rn(v[j].x * r * scale);
        int qy = __float2int_rn(v[j].y * r * scale);
        int qz = __float2int_rn(v[j].z * r * scale);
        int qw = __float2int_rn(v[j].w * r * scale);
        qx = min(max(qx, -128), 127); qy = min(max(qy, -128), 127);
        qz = min(max(qz, -128), 127); qw = min(max(qw, -128), 127);
        ushort4 o;
        o.x = __bfloat16_as_ushort(__float2bfloat16_rn((float)qx));
        o.y = __bfloat16_as_ushort(__float2bfloat16_rn((float)qy));
        o.z = __bfloat16_as_ushort(__float2bfloat16_rn((float)qz));
        o.w = __bfloat16_as_ushort(__float2bfloat16_rn((float)qw));
        qrow[tid + j * 256] = o;
    }
}

// ---------------- bf16 mma.sync GEMM: single-B, 3-stage cp.async, 2 CTAs/SM ----------------
#define BM 128
#define BN 128
#define SROW 144
#define TILEB (128 * SROW)
#define NSTG 3

__device__ __forceinline__ uint32_t smem_u32(const void* p) {
    uint32_t a;
    asm("{ .reg .u64 t; cvta.to.shared.u64 t, %1; cvt.u32.u64 %0, t; }" : "=r"(a) : "l"(p));
    return a;
}
__device__ __forceinline__ void cp16(uint32_t sdst, const void* gsrc) {
    asm volatile("cp.async.cg.shared.global [%0], [%1], 16;\n" :: "r"(sdst), "l"(gsrc) : "memory");
}
__device__ __forceinline__ void cp_commit() { asm volatile("cp.async.commit_group;\n" ::: "memory"); }
template <int N>
__device__ __forceinline__ void cp_wait() {
    asm volatile("cp.async.wait_group %0;\n" :: "n"(N) : "memory");
}
__device__ __forceinline__ void ldsm4(uint32_t* r, uint32_t addr) {
    asm volatile("ldmatrix.sync.aligned.m8n8.x4.shared.b16 {%0,%1,%2,%3}, [%4];"
        : "=r"(r[0]), "=r"(r[1]), "=r"(r[2]), "=r"(r[3]) : "r"(addr));
}
__device__ __forceinline__ void mma_bf16(float* c, const uint32_t* a, const uint32_t* b) {
    asm volatile(
        "mma.sync.aligned.m16n8k16.row.col.f32.bf16.bf16.f32 "
        "{%0,%1,%2,%3},{%4,%5,%6,%7},{%8,%9},{%0,%1,%2,%3};\n"
        : "+f"(c[0]), "+f"(c[1]), "+f"(c[2]), "+f"(c[3])
        : "r"(a[0]), "r"(a[1]), "r"(a[2]), "r"(a[3]), "r"(b[0]), "r"(b[1]));
}

__global__ void __launch_bounds__(256, 2) gemm_bf(
    const __nv_bfloat16* __restrict__ A,
    const __nv_bfloat16* __restrict__ B,
    int K, const float* __restrict__ invA, int wi,
    float* __restrict__ out, int ldo)
{
    extern __shared__ char smem[];
    const int TB = 2 * TILEB;
    const uint32_t sb = smem_u32(smem);
    int tid = threadIdx.x;
    int m0 = blockIdx.y * BM, n0 = blockIdx.x * BN;
    size_t Kb = (size_t)K * 2;
    const char* Ab = (const char*)A + (size_t)m0 * Kb;
    const char* Bb = (const char*)B + (size_t)n0 * Kb;
    int KT = K / 64;

    auto issue = [&](int kt) {
        uint32_t base = sb + (kt % NSTG) * TB;
        size_t k0b = (size_t)kt * 128;
#pragma unroll
        for (int it = 0; it < 4; it++) {
            int c = it * 256 + tid;
            int row = c >> 3;
            int col = (c & 7) * 16;
            uint32_t soff = (uint32_t)(row * SROW + col);
            cp16(base + soff,         Ab + (size_t)row * Kb + k0b + col);
            cp16(base + TILEB + soff, Bb + (size_t)row * Kb + k0b + col);
        }
        cp_commit();
    };

    int wid = tid >> 5, lane = tid & 31;
    int wm = wid >> 2, wn = wid & 3;     // 2 (M) x 4 (N) warps; warp tile 64x32
    int g = lane >> 2, t4 = lane & 3;

    uint32_t offA[4];
#pragma unroll
    for (int im = 0; im < 4; im++)
        offA[im] = (uint32_t)((wm * 64 + im * 16 + (lane & 15)) * SROW + (lane >> 4) * 16);
    uint32_t offB[2];
#pragma unroll
    for (int ib = 0; ib < 2; ib++)
        offB[ib] = (uint32_t)((wn * 32 + ib * 16 + (lane & 7) + ((lane >> 4) & 1) * 8) * SROW
                              + ((lane >> 3) & 1) * 16);

    float acc[4][4][4] = {};

    issue(0);
    issue(1);
    for (int kt = 0; kt < KT; kt++) {
        if (kt == KT - 1) cp_wait<0>(); else cp_wait<1>();
        __syncthreads();
        if (kt + 2 < KT) issue(kt + 2);

        const uint32_t base = sb + (kt % NSTG) * TB;
        const uint32_t AsmB = base, Bsm = base + TILEB;

#pragma unroll
        for (int ks = 0; ks < 4; ks++) {
            const uint32_t kb = ks * 32;
            uint32_t a[4][4];
#pragma unroll
            for (int im = 0; im < 4; im++) ldsm4(a[im], AsmB + offA[im] + kb);
            uint32_t b[2][4];
#pragma unroll
            for (int ib = 0; ib < 2; ib++) ldsm4(b[ib], Bsm + offB[ib] + kb);
#pragma unroll
            for (int ib = 0; ib < 2; ib++)
#pragma unroll
                for (int sub = 0; sub < 2; sub++)
#pragma unroll
                    for (int im = 0; im < 4; im++)
                        mma_bf16(acc[im][ib * 2 + sub], a[im], &b[ib][sub * 2]);
        }
    }

    // epilogue: dequant only (accumulators are exact integers)
    float dq = g_wdq[wi];
#pragma unroll
    for (int im = 0; im < 4; im++) {
#pragma unroll
        for (int h2 = 0; h2 < 2; h2++) {
            int row = m0 + wm * 64 + im * 16 + g + h2 * 8;
            float s = invA[row] * dq;
#pragma unroll
            for (int in = 0; in < 4; in++) {
                int col = n0 + wn * 32 + in * 8 + t4 * 2;
                size_t o = (size_t)row * ldo + col;
                float2 hv = make_float2(acc[im][in][h2 * 2 + 0] * s,
                                        acc[im][in][h2 * 2 + 1] * s);
                *(float2*)(out + o) = hv;
            }
        }
    }
}

// ---------------- launch ----------------
extern "C" void kernel_launch(void* const* d_in, const int* in_sizes, int n_in,
                              void* d_out, int out_size) {
    const float* x  = (const float*)d_in[0];
    const float* w1 = (const float*)d_in[1];
    const float* w2 = (const float*)d_in[2];
    const float* w3 = (const float*)d_in[3];
    float* out = (float*)d_out;

    void *p_w1b, *p_w2b, *p_w3b, *p_xb, *p_hb, *p_t1, *p_t2, *p_isx, *p_ish;
    cudaGetSymbolAddress(&p_w1b, g_w1b);
    cudaGetSymbolAddress(&p_w2b, g_w2b);
    cudaGetSymbolAddress(&p_w3b, g_w3b);
    cudaGetSymbolAddress(&p_xb,  g_xb);
    cudaGetSymbolAddress(&p_hb,  g_hb);
    cudaGetSymbolAddress(&p_t1,  g_t1);
    cudaGetSymbolAddress(&p_t2,  g_t2);
    cudaGetSymbolAddress(&p_isx, g_inv_sx);
    cudaGetSymbolAddress(&p_ish, g_inv_sh);

    const int SMB = NSTG * 2 * TILEB;   // 3 stages * 36 KB = 108 KB -> 2 CTAs/SM
    cudaFuncSetAttribute(gemm_bf, cudaFuncAttributeMaxDynamicSharedMemorySize, SMB);

    // 1) weight scales (fused partial pass + final)
    wabs_partial3<<<dim3(256, 3), 256>>>(w1, w2, w3);
    wscale_final<<<1, 256>>>();

    // 2) ternary weight quantization, one launch for all three
    quant_w3<<<dim3(NW / 1024, 3), 256>>>(w1, w2, w3,
        (__nv_bfloat16*)p_w1b, (__nv_bfloat16*)p_w2b, (__nv_bfloat16*)p_w3b);

    // 3) rmsnorm + int8-grid quant of x
    act_quant_x<<<M_TOK, 256>>>(x, (__nv_bfloat16*)p_xb, (float*)p_isx);

    // 4) GEMM1a: x@w1^T -> t1 ; GEMM1b: x@w2^T -> t2  (each 2 CTAs/SM)
    dim3 g1(F_DIM / BN, M_TOK / BM);     // (64, 64)
    gemm_bf<<<g1, 256, SMB>>>((const __nv_bfloat16*)p_xb, (const __nv_bfloat16*)p_w1b,
                              E_DIM, (const float*)p_isx, 0, (float*)p_t1, F_DIM);
    gemm_bf<<<g1, 256, SMB>>>((const __nv_bfloat16*)p_xb, (const __nv_bfloat16*)p_w2b,
                              E_DIM, (const float*)p_isx, 1, (float*)p_t2, F_DIM);

    // 5) SwiGLU + rmsnorm + quant of h
    act_quant_swiglu<<<M_TOK, 256>>>((const float*)p_t1, (const float*)p_t2,
                                     (__nv_bfloat16*)p_hb, (float*)p_ish);

    // 6) GEMM2: h@w3^T -> out (2 CTAs/SM)
    dim3 g2(E_DIM / BN, M_TOK / BM);     // (16, 64)
    gemm_bf<<<g2, 256, SMB>>>((const __nv_bfloat16*)p_hb, (const __nv_bfloat16*)p_w3b,
                              F_DIM, (const float*)p_ish, 2, out, E_DIM);
}